// round 5
// baseline (speedup 1.0000x reference)
#include <cuda_runtime.h>
#include <math.h>

// Problem constants
#define BB   4
#define TT   2048
#define CC   2048
#define NH   16
#define HD   128
#define MROWS (BB * TT)          // 8192

// ---------------------------------------------------------------------------
// Scratch (device globals — no allocation allowed in kernel_launch)
// ---------------------------------------------------------------------------
__device__ float g_q[BB * NH * TT * HD];    // (b,h,t,d)
__device__ float g_k[BB * NH * TT * HD];
__device__ float g_v[BB * NH * TT * HD];
__device__ float g_att[BB * TT * CC];       // attention output, (b,t,c)

// ---------------------------------------------------------------------------
// SGEMM:  out[i][j] = sum_k A[i][k] * W[j][k] + bias[j]
// A: M x K row-major (M=8192, K=2048), W: N x K row-major (N=2048)
// Tile 128x128x8, 256 threads, 8x8 per thread.
// HEAD_LAYOUT: write out in (b, h, t, d) layout (N-tile == exactly one head).
// ---------------------------------------------------------------------------
template <bool HEAD_LAYOUT>
__global__ __launch_bounds__(256, 2)
void gemm_nt_kernel(const float* __restrict__ A, const float* __restrict__ W,
                    const float* __restrict__ bias, float* __restrict__ out)
{
    const int K = CC;
    __shared__ float As[8][128];
    __shared__ float Bs[8][128];

    const int tid = threadIdx.x;
    const int bx = blockIdx.x;           // N tile (0..15)
    const int by = blockIdx.y;           // M tile (0..63)
    const int tr = tid >> 4;             // 0..15
    const int tc = tid & 15;             // 0..15

    // global->shared load mapping: each thread 1 float4 of A and of W per k-step
    const int lrow = tid >> 1;           // 0..127
    const int lc4  = (tid & 1) * 4;      // 0 or 4
    const float* Ap = A + (size_t)(by * 128 + lrow) * K + lc4;
    const float* Wp = W + (size_t)(bx * 128 + lrow) * K + lc4;

    float acc[8][8];
#pragma unroll
    for (int i = 0; i < 8; i++)
#pragma unroll
        for (int j = 0; j < 8; j++) acc[i][j] = 0.f;

    for (int k0 = 0; k0 < K; k0 += 8) {
        float4 av = *(const float4*)(Ap + k0);
        float4 wv = *(const float4*)(Wp + k0);
        As[lc4 + 0][lrow] = av.x; As[lc4 + 1][lrow] = av.y;
        As[lc4 + 2][lrow] = av.z; As[lc4 + 3][lrow] = av.w;
        Bs[lc4 + 0][lrow] = wv.x; Bs[lc4 + 1][lrow] = wv.y;
        Bs[lc4 + 2][lrow] = wv.z; Bs[lc4 + 3][lrow] = wv.w;
        __syncthreads();

#pragma unroll
        for (int kk = 0; kk < 8; kk++) {
            float4 a0 = *(const float4*)&As[kk][tr * 4];
            float4 a1 = *(const float4*)&As[kk][64 + tr * 4];
            float4 b0 = *(const float4*)&Bs[kk][tc * 4];
            float4 b1 = *(const float4*)&Bs[kk][64 + tc * 4];
            float a[8] = {a0.x, a0.y, a0.z, a0.w, a1.x, a1.y, a1.z, a1.w};
            float b[8] = {b0.x, b0.y, b0.z, b0.w, b1.x, b1.y, b1.z, b1.w};
#pragma unroll
            for (int i = 0; i < 8; i++)
#pragma unroll
                for (int j = 0; j < 8; j++)
                    acc[i][j] = fmaf(a[i], b[j], acc[i][j]);
        }
        __syncthreads();
    }

    // epilogue
#pragma unroll
    for (int i = 0; i < 8; i++) {
        const int rl   = (i < 4) ? (tr * 4 + i) : (64 + tr * 4 + i - 4);
        const int grow = by * 128 + rl;
#pragma unroll
        for (int j = 0; j < 8; j++) {
            const int cl   = (j < 4) ? (tc * 4 + j) : (64 + tc * 4 + j - 4);
            const int gcol = bx * 128 + cl;
            const float val = acc[i][j] + bias[gcol];
            if (HEAD_LAYOUT) {
                const int b = grow >> 11;          // / 2048
                const int t = grow & 2047;
                const int h = gcol >> 7;           // / 128
                const int d = gcol & 127;
                out[(((size_t)(b * NH + h)) * TT + t) * HD + d] = val;
            } else {
                out[(size_t)grow * CC + gcol] = val;
            }
        }
    }
}

// ---------------------------------------------------------------------------
// Flash attention (causal + additive mask), fp32.
// Grid: (T/64, B*H). Block: 256 threads. 64-query x 64-key tiles, d=128.
// ---------------------------------------------------------------------------
struct __align__(16) AttnSmem {
    float Qs[HD][64];     // transposed: [d][q]
    float Ks[HD][64];     // transposed: [d][kv]
    float Vs[64][HD];     // [kv][d]
    float Ss[64][69];     // scores / probabilities (padded, odd stride)
    float row_m[64];
    float row_l[64];
    float row_a[64];
};

__global__ __launch_bounds__(256, 1)
void attn_kernel(const float* __restrict__ q, const float* __restrict__ k,
                 const float* __restrict__ v, const float* __restrict__ mask,
                 float* __restrict__ out)
{
    extern __shared__ char smraw[];
    AttnSmem& sm = *reinterpret_cast<AttnSmem*>(smraw);

    const int tid = threadIdx.x;
    const int qb  = blockIdx.x;               // query tile (0..31)
    const int bh  = blockIdx.y;               // b*NH + h
    const int b   = bh >> 4;
    const int h   = bh & 15;
    const int q0  = qb * 64;
    const float scale = 0.08838834764831845f; // 1/sqrt(128)

    const int tr = tid >> 4;                  // row group 0..15 (4 rows)
    const int tc = tid & 15;                  // col group 0..15

    // ---- load Q tile transposed into smem ----
    const float* qptr = q + ((size_t)bh * TT + q0) * HD;
#pragma unroll
    for (int it = 0; it < 8; it++) {
        const int idx = it * 256 + tid;       // float4 index in 64x128 tile
        const int row = idx & 63;
        const int d   = (idx >> 6) * 4;
        float4 val = *(const float4*)(qptr + row * HD + d);
        sm.Qs[d + 0][row] = val.x; sm.Qs[d + 1][row] = val.y;
        sm.Qs[d + 2][row] = val.z; sm.Qs[d + 3][row] = val.w;
    }
    if (tid < 64) { sm.row_m[tid] = -1e30f; sm.row_l[tid] = 0.f; }

    float oacc[4][8];
#pragma unroll
    for (int i = 0; i < 4; i++)
#pragma unroll
        for (int j = 0; j < 8; j++) oacc[i][j] = 0.f;

    for (int jt = 0; jt <= qb; jt++) {
        const int kv0 = jt * 64;
        const float* kptr = k + ((size_t)bh * TT + kv0) * HD;
        const float* vptr = v + ((size_t)bh * TT + kv0) * HD;

        __syncthreads();   // previous iteration's readers of Ks/Vs/Ss done

        // K tile transposed
#pragma unroll
        for (int it = 0; it < 8; it++) {
            const int idx = it * 256 + tid;
            const int row = idx & 63;
            const int d   = (idx >> 6) * 4;
            float4 val = *(const float4*)(kptr + row * HD + d);
            sm.Ks[d + 0][row] = val.x; sm.Ks[d + 1][row] = val.y;
            sm.Ks[d + 2][row] = val.z; sm.Ks[d + 3][row] = val.w;
        }
        // V tile straight copy
#pragma unroll
        for (int it = 0; it < 8; it++) {
            const int idx = it * 256 + tid;
            ((float4*)sm.Vs)[idx] = ((const float4*)vptr)[idx];
        }
        __syncthreads();

        // ---- S = Q K^T (4x4 per thread) ----
        float sacc[4][4];
#pragma unroll
        for (int i = 0; i < 4; i++)
#pragma unroll
            for (int j = 0; j < 4; j++) sacc[i][j] = 0.f;

#pragma unroll 8
        for (int d = 0; d < HD; d++) {
            float4 av = *(const float4*)&sm.Qs[d][tr * 4];
            float4 bv = *(const float4*)&sm.Ks[d][tc * 4];
            float a[4] = {av.x, av.y, av.z, av.w};
            float bb[4] = {bv.x, bv.y, bv.z, bv.w};
#pragma unroll
            for (int i = 0; i < 4; i++)
#pragma unroll
                for (int j = 0; j < 4; j++)
                    sacc[i][j] = fmaf(a[i], bb[j], sacc[i][j]);
        }

        // scale + additive mask + causal, store to Ss
        float am[4];
#pragma unroll
        for (int j = 0; j < 4; j++) am[j] = mask[b * TT + kv0 + tc * 4 + j];
#pragma unroll
        for (int i = 0; i < 4; i++) {
            const int qg = q0 + tr * 4 + i;
#pragma unroll
            for (int j = 0; j < 4; j++) {
                const int kg = kv0 + tc * 4 + j;
                float s = sacc[i][j] * scale + am[j];
                if (kg > qg) s = -1e30f;
                sm.Ss[tr * 4 + i][tc * 4 + j] = s;
            }
        }
        __syncthreads();

        // ---- online-softmax row statistics (64 threads, one per row) ----
        if (tid < 64) {
            const float m_old = sm.row_m[tid];
            float mx = m_old;
#pragma unroll 8
            for (int j = 0; j < 64; j++) mx = fmaxf(mx, sm.Ss[tid][j]);
            const float alpha = __expf(m_old - mx);
            float l = sm.row_l[tid] * alpha;
#pragma unroll 8
            for (int j = 0; j < 64; j++) {
                const float p = __expf(sm.Ss[tid][j] - mx);
                sm.Ss[tid][j] = p;
                l += p;
            }
            sm.row_m[tid] = mx;
            sm.row_l[tid] = l;
            sm.row_a[tid] = alpha;
        }
        __syncthreads();

        // ---- rescale O and accumulate P @ V (4x8 per thread) ----
        float al[4];
#pragma unroll
        for (int i = 0; i < 4; i++) al[i] = sm.row_a[tr * 4 + i];
#pragma unroll
        for (int i = 0; i < 4; i++)
#pragma unroll
            for (int j = 0; j < 8; j++) oacc[i][j] *= al[i];

#pragma unroll 4
        for (int kv = 0; kv < 64; kv++) {
            float p[4];
#pragma unroll
            for (int i = 0; i < 4; i++) p[i] = sm.Ss[tr * 4 + i][kv];
            float4 v0 = *(const float4*)&sm.Vs[kv][tc * 8];
            float4 v1 = *(const float4*)&sm.Vs[kv][tc * 8 + 4];
            float vv[8] = {v0.x, v0.y, v0.z, v0.w, v1.x, v1.y, v1.z, v1.w};
#pragma unroll
            for (int i = 0; i < 4; i++)
#pragma unroll
                for (int j = 0; j < 8; j++)
                    oacc[i][j] = fmaf(p[i], vv[j], oacc[i][j]);
        }
    }

    // ---- normalize + write out in (b, t, c) layout ----
#pragma unroll
    for (int i = 0; i < 4; i++) {
        const float inv = 1.f / sm.row_l[tr * 4 + i];
        const int tglob = q0 + tr * 4 + i;
        float* op = out + ((size_t)b * TT + tglob) * CC + h * HD + tc * 8;
        float4 r0, r1;
        r0.x = oacc[i][0] * inv; r0.y = oacc[i][1] * inv;
        r0.z = oacc[i][2] * inv; r0.w = oacc[i][3] * inv;
        r1.x = oacc[i][4] * inv; r1.y = oacc[i][5] * inv;
        r1.z = oacc[i][6] * inv; r1.w = oacc[i][7] * inv;
        *(float4*)op = r0;
        *(float4*)(op + 4) = r1;
    }
}

// ---------------------------------------------------------------------------
// Launcher
// ---------------------------------------------------------------------------
extern "C" void kernel_launch(void* const* d_in, const int* in_sizes, int n_in,
                              void* d_out, int out_size)
{
    const float* x    = (const float*)d_in[0];
    const float* mask = (const float*)d_in[1];
    const float* Wq   = (const float*)d_in[2];
    const float* bq   = (const float*)d_in[3];
    const float* Wk   = (const float*)d_in[4];
    const float* bk   = (const float*)d_in[5];
    const float* Wv   = (const float*)d_in[6];
    const float* bv   = (const float*)d_in[7];
    const float* Wp   = (const float*)d_in[8];
    const float* bp   = (const float*)d_in[9];
    float* out = (float*)d_out;

    float *q, *k, *v, *att;
    cudaGetSymbolAddress((void**)&q,   g_q);
    cudaGetSymbolAddress((void**)&k,   g_k);
    cudaGetSymbolAddress((void**)&v,   g_v);
    cudaGetSymbolAddress((void**)&att, g_att);

    cudaFuncSetAttribute(attn_kernel,
                         cudaFuncAttributeMaxDynamicSharedMemorySize,
                         (int)sizeof(AttnSmem));

    const dim3 gg(CC / 128, MROWS / 128);   // (16, 64)

    gemm_nt_kernel<true><<<gg, 256>>>(x, Wq, bq, q);
    gemm_nt_kernel<true><<<gg, 256>>>(x, Wk, bk, k);
    gemm_nt_kernel<true><<<gg, 256>>>(x, Wv, bv, v);

    attn_kernel<<<dim3(TT / 64, BB * NH), 256, sizeof(AttnSmem)>>>(q, k, v, mask, att);

    gemm_nt_kernel<false><<<gg, 256>>>(att, Wp, bp, out);
}

// round 7
// speedup vs baseline: 3.2198x; 3.2198x over previous
#include <cuda_runtime.h>
#include <cuda_bf16.h>
#include <math.h>
#include <stdint.h>
#include <stddef.h>

// Problem constants
#define BB   4
#define TT   2048
#define CC   2048
#define NH   16
#define HD   128
#define MROWS (BB * TT)          // 8192

// ---------------------------------------------------------------------------
// Scratch (device globals)
// ---------------------------------------------------------------------------
__device__ float g_q[BB * NH * TT * HD];    // (b,h,t,d) fp32
__device__ float g_k[BB * NH * TT * HD];
__device__ float g_v[BB * NH * TT * HD];
__device__ float g_att[BB * TT * CC];       // attention output, (b,t,c) fp32

// bf16 hi/lo split buffers
__device__ __nv_bfloat16 g_xh[BB * TT * CC];
__device__ __nv_bfloat16 g_xl[BB * TT * CC];
__device__ __nv_bfloat16 g_ath[BB * TT * CC];
__device__ __nv_bfloat16 g_atl[BB * TT * CC];
__device__ __nv_bfloat16 g_wh[4][CC * CC];
__device__ __nv_bfloat16 g_wl[4][CC * CC];

// ---------------------------------------------------------------------------
// Helpers
// ---------------------------------------------------------------------------
__device__ __forceinline__ uint32_t smem_u32(const void* p) {
    uint32_t a;
    asm("{ .reg .u64 t; cvta.to.shared.u64 t, %1; cvt.u32.u64 %0, t; }"
        : "=r"(a) : "l"(p));
    return a;
}

__device__ __forceinline__ void cp16(uint32_t dst, const void* src) {
    asm volatile("cp.async.cg.shared.global [%0], [%1], 16;"
                 :: "r"(dst), "l"(src) : "memory");
}

__device__ __forceinline__ void ldsm_x4(uint32_t* r, uint32_t addr) {
    asm volatile("ldmatrix.sync.aligned.m8n8.x4.shared.b16 {%0,%1,%2,%3}, [%4];"
        : "=r"(r[0]), "=r"(r[1]), "=r"(r[2]), "=r"(r[3]) : "r"(addr));
}
__device__ __forceinline__ void ldsm_x2(uint32_t* r, uint32_t addr) {
    asm volatile("ldmatrix.sync.aligned.m8n8.x2.shared.b16 {%0,%1}, [%2];"
        : "=r"(r[0]), "=r"(r[1]) : "r"(addr));
}
__device__ __forceinline__ void mma16816(float* c, const uint32_t* a, const uint32_t* b) {
    asm volatile("mma.sync.aligned.m16n8k16.row.col.f32.bf16.bf16.f32 "
        "{%0,%1,%2,%3}, {%4,%5,%6,%7}, {%8,%9}, {%0,%1,%2,%3};"
        : "+f"(c[0]), "+f"(c[1]), "+f"(c[2]), "+f"(c[3])
        : "r"(a[0]), "r"(a[1]), "r"(a[2]), "r"(a[3]), "r"(b[0]), "r"(b[1]));
}

// ---------------------------------------------------------------------------
// fp32 -> bf16 hi/lo split
// ---------------------------------------------------------------------------
__global__ void split_kernel(const float* __restrict__ in,
                             __nv_bfloat16* __restrict__ hi,
                             __nv_bfloat16* __restrict__ lo, int n4)
{
    int i = blockIdx.x * blockDim.x + threadIdx.x;
    if (i >= n4) return;
    float4 v = ((const float4*)in)[i];
    float f[4] = {v.x, v.y, v.z, v.w};
    __align__(8) __nv_bfloat16 h[4];
    __align__(8) __nv_bfloat16 l[4];
#pragma unroll
    for (int j = 0; j < 4; j++) {
        h[j] = __float2bfloat16(f[j]);
        l[j] = __float2bfloat16(f[j] - __bfloat162float(h[j]));
    }
    ((uint2*)hi)[i] = *(uint2*)h;
    ((uint2*)lo)[i] = *(uint2*)l;
}

// ---------------------------------------------------------------------------
// Split-bf16 tensor-core GEMM via mma.sync (HMMA):
//   out[i][j] = sum_k A[i][k] * W[j][k] + bias[j]
// A: 8192x2048 (hi/lo bf16), W: 2048x2048 (hi/lo bf16).
// CTA tile 128x128, BK=64, 3-stage cp.async pipeline, 8 warps (64x32 each).
// Smem tile layout: 128B rows (8x16B chunks), chunk XOR-swizzled by (row&7).
// ---------------------------------------------------------------------------
#define BM 128
#define BN 128
#define BK 64
#define NSTG 3
#define KCH (CC / BK)                 // 32
#define TILE_B 16384                  // 128 rows x 128 bytes
#define STG_B (4 * TILE_B)            // Ah, Al, Wh, Wl
static constexpr unsigned GEMM_SMEM = NSTG * STG_B;   // 196608

__global__ __launch_bounds__(256, 1)
void gemm_tc_kernel(const __nv_bfloat16* __restrict__ Ah,
                    const __nv_bfloat16* __restrict__ Al,
                    const __nv_bfloat16* __restrict__ Wh,
                    const __nv_bfloat16* __restrict__ Wl,
                    const float* __restrict__ bias,
                    float* __restrict__ out,
                    int head_layout)
{
    extern __shared__ char smem[];
    const uint32_t sb = smem_u32(smem);
    const int tid  = threadIdx.x;
    const int lane = tid & 31;
    const int wid  = tid >> 5;
    const int wr   = wid >> 2;          // 0..1  (64-row strip)
    const int wc   = wid & 3;           // 0..3  (32-col strip)
    const int bx = blockIdx.x, by = blockIdx.y;

    const __nv_bfloat16* srcs[4] = {
        Ah + (size_t)by * BM * CC,
        Al + (size_t)by * BM * CC,
        Wh + (size_t)bx * BN * CC,
        Wl + (size_t)bx * BN * CC
    };

    auto load_stage = [&](int stg, int kc) {
        const uint32_t base = sb + stg * STG_B;
#pragma unroll
        for (int ti = 0; ti < 4; ti++) {
            const __nv_bfloat16* src = srcs[ti];
            const uint32_t tb = base + ti * TILE_B;
#pragma unroll
            for (int i = 0; i < 4; i++) {
                const int idx = tid + i * 256;       // 0..1023
                const int row = idx >> 3;
                const int ch  = idx & 7;
                const uint32_t dst = tb + row * 128 + ((ch ^ (row & 7)) << 4);
                cp16(dst, src + (size_t)row * CC + kc + ch * 8);
            }
        }
        asm volatile("cp.async.commit_group;" ::: "memory");
    };

    // ldmatrix lane addressing (constant across k-steps)
    const int a_lr = lane & 15;            // row-within-16
    const int a_hk = lane >> 4;            // k-half select
    uint32_t a_off[4]; int a_sel[4];
#pragma unroll
    for (int mt = 0; mt < 4; mt++) {
        const int r = wr * 64 + mt * 16 + a_lr;
        a_off[mt] = r * 128;
        a_sel[mt] = r & 7;
    }
    const int b_lr = lane & 7;
    const int b_hk = (lane >> 3) & 1;
    uint32_t b_off[4]; int b_sel[4];
#pragma unroll
    for (int nt = 0; nt < 4; nt++) {
        const int r = wc * 32 + nt * 8 + b_lr;
        b_off[nt] = r * 128;
        b_sel[nt] = r & 7;
    }

    float c[4][4][4];
#pragma unroll
    for (int mt = 0; mt < 4; mt++)
#pragma unroll
        for (int nt = 0; nt < 4; nt++)
#pragma unroll
            for (int i = 0; i < 4; i++) c[mt][nt][i] = 0.f;

    load_stage(0, 0);
    load_stage(1, BK);

    for (int chk = 0; chk < KCH; chk++) {
        if (chk + 1 < KCH) asm volatile("cp.async.wait_group 1;" ::: "memory");
        else               asm volatile("cp.async.wait_group 0;" ::: "memory");
        __syncthreads();

        const uint32_t base = sb + (chk % NSTG) * STG_B;
#pragma unroll
        for (int ks = 0; ks < 4; ks++) {
            uint32_t ah[4][4], al[4][4], bh[4][2], bl[4][2];
            const int ca = ks * 2 + a_hk;
            const int cb = ks * 2 + b_hk;
#pragma unroll
            for (int mt = 0; mt < 4; mt++) {
                const uint32_t sw = (uint32_t)((ca ^ a_sel[mt]) << 4);
                ldsm_x4(ah[mt], base + a_off[mt] + sw);
                ldsm_x4(al[mt], base + TILE_B + a_off[mt] + sw);
            }
#pragma unroll
            for (int nt = 0; nt < 4; nt++) {
                const uint32_t sw = (uint32_t)((cb ^ b_sel[nt]) << 4);
                ldsm_x2(bh[nt], base + 2 * TILE_B + b_off[nt] + sw);
                ldsm_x2(bl[nt], base + 3 * TILE_B + b_off[nt] + sw);
            }
#pragma unroll
            for (int mt = 0; mt < 4; mt++)
#pragma unroll
                for (int nt = 0; nt < 4; nt++) {
                    mma16816(c[mt][nt], ah[mt], bh[nt]);   // hi*hi
                    mma16816(c[mt][nt], ah[mt], bl[nt]);   // hi*lo
                    mma16816(c[mt][nt], al[mt], bh[nt]);   // lo*hi
                }
        }

        if (chk + 2 < KCH) load_stage((chk + 2) % NSTG, (chk + 2) * BK);
    }

    // ---- epilogue ----
    const int t4 = lane >> 2;
    const int t2 = (lane & 3) * 2;
#pragma unroll
    for (int mt = 0; mt < 4; mt++) {
        const int r0 = by * BM + wr * 64 + mt * 16 + t4;
        const int r1 = r0 + 8;
#pragma unroll
        for (int nt = 0; nt < 4; nt++) {
            const int col = bx * BN + wc * 32 + nt * 8 + t2;
            const float bi0 = bias[col], bi1 = bias[col + 1];
            float2 v0 = {c[mt][nt][0] + bi0, c[mt][nt][1] + bi1};
            float2 v1 = {c[mt][nt][2] + bi0, c[mt][nt][3] + bi1};
            if (head_layout) {
                const int d = col & 127;               // head = bx
                const int b0 = r0 >> 11, t0 = r0 & 2047;
                const int b1 = r1 >> 11, t1 = r1 & 2047;
                *(float2*)(out + (((size_t)(b0 * NH + bx)) * TT + t0) * HD + d) = v0;
                *(float2*)(out + (((size_t)(b1 * NH + bx)) * TT + t1) * HD + d) = v1;
            } else {
                *(float2*)(out + (size_t)r0 * CC + col) = v0;
                *(float2*)(out + (size_t)r1 * CC + col) = v1;
            }
        }
    }
}

// ---------------------------------------------------------------------------
// Flash attention (causal + additive mask), fp32.
// Grid: (T/64, B*H). Block: 256 threads. 64-query x 64-key tiles, d=128.
// ---------------------------------------------------------------------------
struct __align__(16) AttnSmem {
    float Qs[HD][64];     // transposed: [d][q]
    float Ks[HD][64];     // transposed: [d][kv]
    float Vs[64][HD];     // [kv][d]
    float Ss[64][69];     // scores / probabilities (padded, odd stride)
    float row_m[64];
    float row_l[64];
    float row_a[64];
};

__global__ __launch_bounds__(256, 1)
void attn_kernel(const float* __restrict__ q, const float* __restrict__ k,
                 const float* __restrict__ v, const float* __restrict__ mask,
                 float* __restrict__ out)
{
    extern __shared__ char smraw[];
    AttnSmem& sm = *reinterpret_cast<AttnSmem*>(smraw);

    const int tid = threadIdx.x;
    const int qb  = blockIdx.x;
    const int bh  = blockIdx.y;
    const int b   = bh >> 4;
    const int h   = bh & 15;
    const int q0  = qb * 64;
    const float scale = 0.08838834764831845f; // 1/sqrt(128)

    const int tr = tid >> 4;
    const int tc = tid & 15;

    const float* qptr = q + ((size_t)bh * TT + q0) * HD;
#pragma unroll
    for (int it = 0; it < 8; it++) {
        const int idx = it * 256 + tid;
        const int row = idx & 63;
        const int d   = (idx >> 6) * 4;
        float4 val = *(const float4*)(qptr + row * HD + d);
        sm.Qs[d + 0][row] = val.x; sm.Qs[d + 1][row] = val.y;
        sm.Qs[d + 2][row] = val.z; sm.Qs[d + 3][row] = val.w;
    }
    if (tid < 64) { sm.row_m[tid] = -1e30f; sm.row_l[tid] = 0.f; }

    float oacc[4][8];
#pragma unroll
    for (int i = 0; i < 4; i++)
#pragma unroll
        for (int j = 0; j < 8; j++) oacc[i][j] = 0.f;

    for (int jt = 0; jt <= qb; jt++) {
        const int kv0 = jt * 64;
        const float* kptr = k + ((size_t)bh * TT + kv0) * HD;
        const float* vptr = v + ((size_t)bh * TT + kv0) * HD;

        __syncthreads();

#pragma unroll
        for (int it = 0; it < 8; it++) {
            const int idx = it * 256 + tid;
            const int row = idx & 63;
            const int d   = (idx >> 6) * 4;
            float4 val = *(const float4*)(kptr + row * HD + d);
            sm.Ks[d + 0][row] = val.x; sm.Ks[d + 1][row] = val.y;
            sm.Ks[d + 2][row] = val.z; sm.Ks[d + 3][row] = val.w;
        }
#pragma unroll
        for (int it = 0; it < 8; it++) {
            const int idx = it * 256 + tid;
            ((float4*)sm.Vs)[idx] = ((const float4*)vptr)[idx];
        }
        __syncthreads();

        // ---- S = Q K^T ----
        float sacc[4][4];
#pragma unroll
        for (int i = 0; i < 4; i++)
#pragma unroll
            for (int j = 0; j < 4; j++) sacc[i][j] = 0.f;

#pragma unroll 8
        for (int d = 0; d < HD; d++) {
            float4 av = *(const float4*)&sm.Qs[d][tr * 4];
            float4 bv = *(const float4*)&sm.Ks[d][tc * 4];
            float a[4] = {av.x, av.y, av.z, av.w};
            float bb[4] = {bv.x, bv.y, bv.z, bv.w};
#pragma unroll
            for (int i = 0; i < 4; i++)
#pragma unroll
                for (int j = 0; j < 4; j++)
                    sacc[i][j] = fmaf(a[i], bb[j], sacc[i][j]);
        }

        float am[4];
#pragma unroll
        for (int j = 0; j < 4; j++) am[j] = mask[b * TT + kv0 + tc * 4 + j];
#pragma unroll
        for (int i = 0; i < 4; i++) {
            const int qg = q0 + tr * 4 + i;
#pragma unroll
            for (int j = 0; j < 4; j++) {
                const int kg = kv0 + tc * 4 + j;
                float s = sacc[i][j] * scale + am[j];
                if (kg > qg) s = -1e30f;
                sm.Ss[tr * 4 + i][tc * 4 + j] = s;
            }
        }
        __syncthreads();

        // ---- online-softmax row stats (4 threads per row) ----
        {
            const int row  = tid >> 2;
            const int part = tid & 3;
            const float m_old = sm.row_m[row];
            float* srow = sm.Ss[row];
            float mx = -1e30f;
#pragma unroll
            for (int j = 0; j < 16; j++) mx = fmaxf(mx, srow[part * 16 + j]);
            mx = fmaxf(mx, __shfl_xor_sync(0xffffffffu, mx, 1));
            mx = fmaxf(mx, __shfl_xor_sync(0xffffffffu, mx, 2));
            mx = fmaxf(mx, m_old);
            float l = 0.f;
#pragma unroll
            for (int j = 0; j < 16; j++) {
                const float p = __expf(srow[part * 16 + j] - mx);
                srow[part * 16 + j] = p;
                l += p;
            }
            l += __shfl_xor_sync(0xffffffffu, l, 1);
            l += __shfl_xor_sync(0xffffffffu, l, 2);
            if (part == 0) {
                const float alpha = __expf(m_old - mx);
                sm.row_a[row] = alpha;
                sm.row_l[row] = sm.row_l[row] * alpha + l;
                sm.row_m[row] = mx;
            }
        }
        __syncthreads();

        // ---- rescale O, accumulate P @ V ----
        float al[4];
#pragma unroll
        for (int i = 0; i < 4; i++) al[i] = sm.row_a[tr * 4 + i];
#pragma unroll
        for (int i = 0; i < 4; i++)
#pragma unroll
            for (int j = 0; j < 8; j++) oacc[i][j] *= al[i];

#pragma unroll 4
        for (int kv = 0; kv < 64; kv++) {
            float p[4];
#pragma unroll
            for (int i = 0; i < 4; i++) p[i] = sm.Ss[tr * 4 + i][kv];
            float4 v0 = *(const float4*)&sm.Vs[kv][tc * 8];
            float4 v1 = *(const float4*)&sm.Vs[kv][tc * 8 + 4];
            float vv[8] = {v0.x, v0.y, v0.z, v0.w, v1.x, v1.y, v1.z, v1.w};
#pragma unroll
            for (int i = 0; i < 4; i++)
#pragma unroll
                for (int j = 0; j < 8; j++)
                    oacc[i][j] = fmaf(p[i], vv[j], oacc[i][j]);
        }
    }

#pragma unroll
    for (int i = 0; i < 4; i++) {
        const float inv = 1.f / sm.row_l[tr * 4 + i];
        const int tglob = q0 + tr * 4 + i;
        float* op = out + ((size_t)b * TT + tglob) * CC + h * HD + tc * 8;
        float4 r0, r1;
        r0.x = oacc[i][0] * inv; r0.y = oacc[i][1] * inv;
        r0.z = oacc[i][2] * inv; r0.w = oacc[i][3] * inv;
        r1.x = oacc[i][4] * inv; r1.y = oacc[i][5] * inv;
        r1.z = oacc[i][6] * inv; r1.w = oacc[i][7] * inv;
        *(float4*)op = r0;
        *(float4*)(op + 4) = r1;
    }
}

// ---------------------------------------------------------------------------
// Launcher
// ---------------------------------------------------------------------------
extern "C" void kernel_launch(void* const* d_in, const int* in_sizes, int n_in,
                              void* d_out, int out_size)
{
    const float* x    = (const float*)d_in[0];
    const float* mask = (const float*)d_in[1];
    const float* bq   = (const float*)d_in[3];
    const float* bk   = (const float*)d_in[5];
    const float* bv   = (const float*)d_in[7];
    const float* bp   = (const float*)d_in[9];
    const float* W[4] = {(const float*)d_in[2], (const float*)d_in[4],
                         (const float*)d_in[6], (const float*)d_in[8]};
    float* out = (float*)d_out;

    float *q, *k, *v, *att;
    __nv_bfloat16 *xh, *xl, *ath, *atl, *wh, *wl;
    cudaGetSymbolAddress((void**)&q,   g_q);
    cudaGetSymbolAddress((void**)&k,   g_k);
    cudaGetSymbolAddress((void**)&v,   g_v);
    cudaGetSymbolAddress((void**)&att, g_att);
    cudaGetSymbolAddress((void**)&xh,  g_xh);
    cudaGetSymbolAddress((void**)&xl,  g_xl);
    cudaGetSymbolAddress((void**)&ath, g_ath);
    cudaGetSymbolAddress((void**)&atl, g_atl);
    cudaGetSymbolAddress((void**)&wh,  g_wh);
    cudaGetSymbolAddress((void**)&wl,  g_wl);

    cudaFuncSetAttribute(gemm_tc_kernel,
                         cudaFuncAttributeMaxDynamicSharedMemorySize, GEMM_SMEM);
    cudaFuncSetAttribute(attn_kernel,
                         cudaFuncAttributeMaxDynamicSharedMemorySize,
                         (int)sizeof(AttnSmem));

    // 1. split x and weights into bf16 hi/lo
    {
        const int n4x = (BB * TT * CC) / 4;
        split_kernel<<<(n4x + 255) / 256, 256>>>(x, xh, xl, n4x);
        const int n4w = (CC * CC) / 4;
        for (int i = 0; i < 4; i++)
            split_kernel<<<(n4w + 255) / 256, 256>>>(
                W[i], wh + (size_t)i * CC * CC, wl + (size_t)i * CC * CC, n4w);
    }

    const dim3 gg(CC / BN, MROWS / BM);   // (16, 64)

    // 2. QKV projections (head layout)
    gemm_tc_kernel<<<gg, 256, GEMM_SMEM>>>(xh, xl, wh + 0 * (size_t)CC * CC,
                                           wl + 0 * (size_t)CC * CC, bq, q, 1);
    gemm_tc_kernel<<<gg, 256, GEMM_SMEM>>>(xh, xl, wh + 1 * (size_t)CC * CC,
                                           wl + 1 * (size_t)CC * CC, bk, k, 1);
    gemm_tc_kernel<<<gg, 256, GEMM_SMEM>>>(xh, xl, wh + 2 * (size_t)CC * CC,
                                           wl + 2 * (size_t)CC * CC, bv, v, 1);

    // 3. attention
    attn_kernel<<<dim3(TT / 64, BB * NH), 256, sizeof(AttnSmem)>>>(q, k, v, mask, att);

    // 4. split attention output, output projection
    {
        const int n4 = (BB * TT * CC) / 4;
        split_kernel<<<(n4 + 255) / 256, 256>>>(att, ath, atl, n4);
    }
    gemm_tc_kernel<<<gg, 256, GEMM_SMEM>>>(ath, atl, wh + 3 * (size_t)CC * CC,
                                           wl + 3 * (size_t)CC * CC, bp, out, 0);
}

// round 9
// speedup vs baseline: 5.7867x; 1.7972x over previous
#include <cuda_runtime.h>
#include <cuda_bf16.h>
#include <math.h>
#include <stdint.h>
#include <stddef.h>

// Problem constants
#define BB   4
#define TT   2048
#define CC   2048
#define NH   16
#define HD   128
#define MROWS (BB * TT)          // 8192
#define LOG2E 1.4426950408889634f
#define QSCALE 0.12751743502016435f   // (1/sqrt(128)) * log2(e)

// ---------------------------------------------------------------------------
// Scratch (device globals)
// ---------------------------------------------------------------------------
__device__ __nv_bfloat16 g_xh[BB * TT * CC];
__device__ __nv_bfloat16 g_xl[BB * TT * CC];
__device__ __nv_bfloat16 g_ath[BB * TT * CC];
__device__ __nv_bfloat16 g_atl[BB * TT * CC];
__device__ __nv_bfloat16 g_wh[4][CC * CC];
__device__ __nv_bfloat16 g_wl[4][CC * CC];
__device__ __nv_bfloat16 g_qh[BB * NH * TT * HD];   // (b,h,t,d)
__device__ __nv_bfloat16 g_ql[BB * NH * TT * HD];
__device__ __nv_bfloat16 g_kh[BB * NH * TT * HD];
__device__ __nv_bfloat16 g_kl[BB * NH * TT * HD];
__device__ __nv_bfloat16 g_vh[BB * NH * TT * HD];
__device__ __nv_bfloat16 g_vl[BB * NH * TT * HD];

// ---------------------------------------------------------------------------
// Helpers
// ---------------------------------------------------------------------------
__device__ __forceinline__ uint32_t smem_u32(const void* p) {
    uint32_t a;
    asm("{ .reg .u64 t; cvta.to.shared.u64 t, %1; cvt.u32.u64 %0, t; }"
        : "=r"(a) : "l"(p));
    return a;
}
__device__ __forceinline__ void cp16(uint32_t dst, const void* src) {
    asm volatile("cp.async.cg.shared.global [%0], [%1], 16;"
                 :: "r"(dst), "l"(src) : "memory");
}
__device__ __forceinline__ void ldsm_x4(uint32_t* r, uint32_t addr) {
    asm volatile("ldmatrix.sync.aligned.m8n8.x4.shared.b16 {%0,%1,%2,%3}, [%4];"
        : "=r"(r[0]), "=r"(r[1]), "=r"(r[2]), "=r"(r[3]) : "r"(addr));
}
__device__ __forceinline__ void ldsm_x4t(uint32_t* r, uint32_t addr) {
    asm volatile("ldmatrix.sync.aligned.m8n8.x4.trans.shared.b16 {%0,%1,%2,%3}, [%4];"
        : "=r"(r[0]), "=r"(r[1]), "=r"(r[2]), "=r"(r[3]) : "r"(addr));
}
__device__ __forceinline__ void ldsm_x2(uint32_t* r, uint32_t addr) {
    asm volatile("ldmatrix.sync.aligned.m8n8.x2.shared.b16 {%0,%1}, [%2];"
        : "=r"(r[0]), "=r"(r[1]) : "r"(addr));
}
__device__ __forceinline__ void mma16816(float* c, const uint32_t* a, const uint32_t* b) {
    asm volatile("mma.sync.aligned.m16n8k16.row.col.f32.bf16.bf16.f32 "
        "{%0,%1,%2,%3}, {%4,%5,%6,%7}, {%8,%9}, {%0,%1,%2,%3};"
        : "+f"(c[0]), "+f"(c[1]), "+f"(c[2]), "+f"(c[3])
        : "r"(a[0]), "r"(a[1]), "r"(a[2]), "r"(a[3]), "r"(b[0]), "r"(b[1]));
}
// pack (a,b) -> bf16x2 hi word + lo word (a in low half)
__device__ __forceinline__ void split_pack(float a, float b, uint32_t& h, uint32_t& l) {
    __nv_bfloat16 ah = __float2bfloat16(a);
    __nv_bfloat16 bh = __float2bfloat16(b);
    __nv_bfloat162 hh; hh.x = ah; hh.y = bh;
    h = *(uint32_t*)&hh;
    __nv_bfloat162 ll;
    ll.x = __float2bfloat16(a - __bfloat162float(ah));
    ll.y = __float2bfloat16(b - __bfloat162float(bh));
    l = *(uint32_t*)&ll;
}

// ---------------------------------------------------------------------------
// fp32 -> bf16 hi/lo split
// ---------------------------------------------------------------------------
__global__ void split_kernel(const float* __restrict__ in,
                             __nv_bfloat16* __restrict__ hi,
                             __nv_bfloat16* __restrict__ lo, int n4)
{
    int i = blockIdx.x * blockDim.x + threadIdx.x;
    if (i >= n4) return;
    float4 v = ((const float4*)in)[i];
    float f[4] = {v.x, v.y, v.z, v.w};
    __align__(8) __nv_bfloat16 h[4];
    __align__(8) __nv_bfloat16 l[4];
#pragma unroll
    for (int j = 0; j < 4; j++) {
        h[j] = __float2bfloat16(f[j]);
        l[j] = __float2bfloat16(f[j] - __bfloat162float(h[j]));
    }
    ((uint2*)hi)[i] = *(uint2*)h;
    ((uint2*)lo)[i] = *(uint2*)l;
}

// ---------------------------------------------------------------------------
// Split-bf16 tensor-core GEMM: out[i][j] = (sum_k A[i][k]*W[j][k] + bias[j])*escale
// mode 0: fp32, row-major flat out.  mode 1: bf16 hi/lo, (b,h,t,d) head layout.
// CTA tile 128x128, BK=64, 3-stage cp.async pipeline, 8 warps (64x32 each).
// ---------------------------------------------------------------------------
#define BM 128
#define BN 128
#define BK 64
#define NSTG 3
#define KCH (CC / BK)                 // 32
#define TILE_B 16384                  // 128 rows x 128 bytes
#define STG_B (4 * TILE_B)
static constexpr unsigned GEMM_SMEM = NSTG * STG_B;   // 196608

__global__ __launch_bounds__(256, 1)
void gemm_tc_kernel(const __nv_bfloat16* __restrict__ Ah,
                    const __nv_bfloat16* __restrict__ Al,
                    const __nv_bfloat16* __restrict__ Wh,
                    const __nv_bfloat16* __restrict__ Wl,
                    const float* __restrict__ bias, float escale,
                    float* __restrict__ outf,
                    __nv_bfloat16* __restrict__ outh,
                    __nv_bfloat16* __restrict__ outl,
                    int mode)
{
    extern __shared__ char smem[];
    const uint32_t sb = smem_u32(smem);
    const int tid  = threadIdx.x;
    const int lane = tid & 31;
    const int wid  = tid >> 5;
    const int wr   = wid >> 2;
    const int wc   = wid & 3;
    const int bx = blockIdx.x, by = blockIdx.y;

    const __nv_bfloat16* srcs[4] = {
        Ah + (size_t)by * BM * CC,
        Al + (size_t)by * BM * CC,
        Wh + (size_t)bx * BN * CC,
        Wl + (size_t)bx * BN * CC
    };

    auto load_stage = [&](int stg, int kc) {
        const uint32_t base = sb + stg * STG_B;
#pragma unroll
        for (int ti = 0; ti < 4; ti++) {
            const __nv_bfloat16* src = srcs[ti];
            const uint32_t tb = base + ti * TILE_B;
#pragma unroll
            for (int i = 0; i < 4; i++) {
                const int idx = tid + i * 256;
                const int row = idx >> 3;
                const int ch  = idx & 7;
                const uint32_t dst = tb + row * 128 + ((ch ^ (row & 7)) << 4);
                cp16(dst, src + (size_t)row * CC + kc + ch * 8);
            }
        }
        asm volatile("cp.async.commit_group;" ::: "memory");
    };

    const int a_lr = lane & 15;
    const int a_hk = lane >> 4;
    uint32_t a_off[4]; int a_sel[4];
#pragma unroll
    for (int mt = 0; mt < 4; mt++) {
        const int r = wr * 64 + mt * 16 + a_lr;
        a_off[mt] = r * 128;
        a_sel[mt] = r & 7;
    }
    const int b_lr = lane & 7;
    const int b_hk = (lane >> 3) & 1;
    uint32_t b_off[4]; int b_sel[4];
#pragma unroll
    for (int nt = 0; nt < 4; nt++) {
        const int r = wc * 32 + nt * 8 + b_lr;
        b_off[nt] = r * 128;
        b_sel[nt] = r & 7;
    }

    float c[4][4][4];
#pragma unroll
    for (int mt = 0; mt < 4; mt++)
#pragma unroll
        for (int nt = 0; nt < 4; nt++)
#pragma unroll
            for (int i = 0; i < 4; i++) c[mt][nt][i] = 0.f;

    load_stage(0, 0);
    load_stage(1, BK);

    for (int chk = 0; chk < KCH; chk++) {
        if (chk + 1 < KCH) asm volatile("cp.async.wait_group 1;" ::: "memory");
        else               asm volatile("cp.async.wait_group 0;" ::: "memory");
        __syncthreads();

        const uint32_t base = sb + (chk % NSTG) * STG_B;
#pragma unroll
        for (int ks = 0; ks < 4; ks++) {
            uint32_t ah[4][4], al[4][4], bh[4][2], bl[4][2];
            const int ca = ks * 2 + a_hk;
            const int cb = ks * 2 + b_hk;
#pragma unroll
            for (int mt = 0; mt < 4; mt++) {
                const uint32_t sw = (uint32_t)((ca ^ a_sel[mt]) << 4);
                ldsm_x4(ah[mt], base + a_off[mt] + sw);
                ldsm_x4(al[mt], base + TILE_B + a_off[mt] + sw);
            }
#pragma unroll
            for (int nt = 0; nt < 4; nt++) {
                const uint32_t sw = (uint32_t)((cb ^ b_sel[nt]) << 4);
                ldsm_x2(bh[nt], base + 2 * TILE_B + b_off[nt] + sw);
                ldsm_x2(bl[nt], base + 3 * TILE_B + b_off[nt] + sw);
            }
#pragma unroll
            for (int mt = 0; mt < 4; mt++)
#pragma unroll
                for (int nt = 0; nt < 4; nt++) {
                    mma16816(c[mt][nt], ah[mt], bh[nt]);
                    mma16816(c[mt][nt], ah[mt], bl[nt]);
                    mma16816(c[mt][nt], al[mt], bh[nt]);
                }
        }

        if (chk + 2 < KCH) load_stage((chk + 2) % NSTG, (chk + 2) * BK);
    }

    // ---- epilogue ----
    const int t4 = lane >> 2;
    const int t2 = (lane & 3) * 2;
#pragma unroll
    for (int mt = 0; mt < 4; mt++) {
        const int r0 = by * BM + wr * 64 + mt * 16 + t4;
        const int r1 = r0 + 8;
#pragma unroll
        for (int nt = 0; nt < 4; nt++) {
            const int col = bx * BN + wc * 32 + nt * 8 + t2;
            const float bi0 = bias[col], bi1 = bias[col + 1];
            float v00 = (c[mt][nt][0] + bi0) * escale;
            float v01 = (c[mt][nt][1] + bi1) * escale;
            float v10 = (c[mt][nt][2] + bi0) * escale;
            float v11 = (c[mt][nt][3] + bi1) * escale;
            if (mode) {
                const int d = col & 127;               // head = bx
                const int b0 = r0 >> 11, t0 = r0 & 2047;
                const int b1 = r1 >> 11, t1 = r1 & 2047;
                const size_t i0 = (((size_t)(b0 * NH + bx)) * TT + t0) * HD + d;
                const size_t i1 = (((size_t)(b1 * NH + bx)) * TT + t1) * HD + d;
                uint32_t ph, pl;
                split_pack(v00, v01, ph, pl);
                *(uint32_t*)&outh[i0] = ph; *(uint32_t*)&outl[i0] = pl;
                split_pack(v10, v11, ph, pl);
                *(uint32_t*)&outh[i1] = ph; *(uint32_t*)&outl[i1] = pl;
            } else {
                float2 v0 = {v00, v01}, v1 = {v10, v11};
                *(float2*)(outf + (size_t)r0 * CC + col) = v0;
                *(float2*)(outf + (size_t)r1 * CC + col) = v1;
            }
        }
    }
}

// ---------------------------------------------------------------------------
// Tensor-core flash attention (FA2-style), split-bf16, exp2 domain.
// Grid: (T/128, B*H). 256 threads = 8 warps x 16 query rows.
// KV tiles of 64, double-buffered cp.async.
// Smem: Qh[0:32K], Ql[32K:64K], stage s at 64K + 64K*s:
//       {Kh:0, Kl:16K, Vh:32K, Vl:48K}. Rows 256B, 16B-chunk XOR swizzle.
// ---------------------------------------------------------------------------
static constexpr unsigned ATT_SMEM = 196608;

__global__ __launch_bounds__(256, 1)
void attn_tc_kernel(const __nv_bfloat16* __restrict__ qh, const __nv_bfloat16* __restrict__ ql,
                    const __nv_bfloat16* __restrict__ kh, const __nv_bfloat16* __restrict__ kl,
                    const __nv_bfloat16* __restrict__ vh, const __nv_bfloat16* __restrict__ vl,
                    const float* __restrict__ mask,
                    __nv_bfloat16* __restrict__ outh, __nv_bfloat16* __restrict__ outl)
{
    extern __shared__ char smem[];
    const uint32_t sb = smem_u32(smem);
    const int tid = threadIdx.x, lane = tid & 31, warp = tid >> 5;
    const int qb = gridDim.x - 1 - blockIdx.x;     // long CTAs first
    const int bh = blockIdx.y;
    const int b = bh >> 4, h = bh & 15;
    const int q0 = qb * 128;
    const int jmax = 2 * qb + 2;
    const size_t bhoff = (size_t)bh * TT * HD;

    // ---- Q tile load (hi + lo) ----
    {
        const __nv_bfloat16* s0 = qh + bhoff + (size_t)q0 * HD;
        const __nv_bfloat16* s1 = ql + bhoff + (size_t)q0 * HD;
#pragma unroll
        for (int i = 0; i < 8; i++) {
            const int idx = tid + i * 256;          // 2048 chunks per matrix
            const int r = idx >> 4, ch = idx & 15;
            const uint32_t off = r * 256 + ((ch ^ (r & 7)) << 4);
            cp16(sb + off,         s0 + (size_t)r * HD + ch * 8);
            cp16(sb + 32768 + off, s1 + (size_t)r * HD + ch * 8);
        }
        asm volatile("cp.async.commit_group;" ::: "memory");
    }

    auto loadKV = [&](int j, int st) {
        const uint32_t base = sb + 65536 + st * 65536;
        const int kv0 = j * 64;
        const __nv_bfloat16* srcs[4] = {
            kh + bhoff + (size_t)kv0 * HD, kl + bhoff + (size_t)kv0 * HD,
            vh + bhoff + (size_t)kv0 * HD, vl + bhoff + (size_t)kv0 * HD };
#pragma unroll
        for (int i = 0; i < 16; i++) {
            const int idx = tid + i * 256;          // 4096
            const int mat = idx >> 10, r = (idx >> 4) & 63, ch = idx & 15;
            cp16(base + mat * 16384 + r * 256 + ((ch ^ (r & 7)) << 4),
                 srcs[mat] + (size_t)r * HD + ch * 8);
        }
        asm volatile("cp.async.commit_group;" ::: "memory");
    };

    loadKV(0, 0);
    loadKV(1, 1);

    float o[16][4];
#pragma unroll
    for (int n = 0; n < 16; n++)
#pragma unroll
        for (int i = 0; i < 4; i++) o[n][i] = 0.f;
    float m0 = -1e30f, m1 = -1e30f, l0 = 0.f, l1 = 0.f;

    // ldmatrix lane addressing
    const int qrow  = warp * 16 + (lane & 15);
    const uint32_t a_base = qrow * 256;
    const int a_sel = qrow & 7;
    const int a_kh  = lane >> 4;
    const int kb_rloc = ((lane >> 4) << 3) + (lane & 7);   // K (QK B-operand)
    const int kb_ch   = (lane >> 3) & 1;
    const int v_rloc  = lane & 15;                          // V (PV B-operand, trans)
    const int v_chh   = lane >> 4;

    const int qg0 = q0 + warp * 16 + (lane >> 2);
    const int qg1 = qg0 + 8;

    for (int j = 0; j < jmax; j++) {
        const int kv0 = j * 64;
        const int st = j & 1;
        if (j + 1 < jmax) asm volatile("cp.async.wait_group 1;" ::: "memory");
        else              asm volatile("cp.async.wait_group 0;" ::: "memory");
        __syncthreads();

        const uint32_t KhB = sb + 65536 + st * 65536;
        const uint32_t KlB = KhB + 16384;
        const uint32_t VhB = KhB + 32768;
        const uint32_t VlB = KhB + 49152;

        // ---- S = Q K^T (3 split passes), 16x64 per warp ----
        float s[8][4];
#pragma unroll
        for (int n = 0; n < 8; n++)
#pragma unroll
            for (int i = 0; i < 4; i++) s[n][i] = 0.f;

#pragma unroll
        for (int ks = 0; ks < 8; ks++) {
            uint32_t qfh[4], qfl[4];
            const uint32_t ca = (uint32_t)(((2 * ks + a_kh) ^ a_sel) << 4);
            ldsm_x4(qfh, sb + a_base + ca);
            ldsm_x4(qfl, sb + 32768 + a_base + ca);
            uint32_t kfh[16], kfl[16];
#pragma unroll
            for (int i = 0; i < 4; i++) {
                const int r = 16 * i + kb_rloc;
                const uint32_t off = r * 256 + (((2 * ks + kb_ch) ^ (r & 7)) << 4);
                ldsm_x4(&kfh[4 * i], KhB + off);
                ldsm_x4(&kfl[4 * i], KlB + off);
            }
#pragma unroll
            for (int n = 0; n < 8; n++) {
                mma16816(s[n], qfh, &kfh[2 * n]);
                mma16816(s[n], qfh, &kfl[2 * n]);
                mma16816(s[n], qfl, &kfh[2 * n]);
            }
        }

        // ---- mask + causal ----
        const bool need_mask = (j >= 2 * qb);
#pragma unroll
        for (int n = 0; n < 8; n++) {
            const int kg = kv0 + 8 * n + 2 * (lane & 3);
            const float2 mv = *(const float2*)&mask[b * TT + kg];
            const float am0 = mv.x * LOG2E, am1 = mv.y * LOG2E;
            s[n][0] += am0; s[n][1] += am1;
            s[n][2] += am0; s[n][3] += am1;
            if (need_mask) {
                if (kg     > qg0) s[n][0] = -1e30f;
                if (kg + 1 > qg0) s[n][1] = -1e30f;
                if (kg     > qg1) s[n][2] = -1e30f;
                if (kg + 1 > qg1) s[n][3] = -1e30f;
            }
        }

        // ---- online softmax (quad-local) ----
        float mx0 = m0, mx1 = m1;
#pragma unroll
        for (int n = 0; n < 8; n++) {
            mx0 = fmaxf(mx0, fmaxf(s[n][0], s[n][1]));
            mx1 = fmaxf(mx1, fmaxf(s[n][2], s[n][3]));
        }
        mx0 = fmaxf(mx0, __shfl_xor_sync(0xffffffffu, mx0, 1));
        mx0 = fmaxf(mx0, __shfl_xor_sync(0xffffffffu, mx0, 2));
        mx1 = fmaxf(mx1, __shfl_xor_sync(0xffffffffu, mx1, 1));
        mx1 = fmaxf(mx1, __shfl_xor_sync(0xffffffffu, mx1, 2));
        const float al0 = exp2f(m0 - mx0);
        const float al1 = exp2f(m1 - mx1);
        m0 = mx0; m1 = mx1;
        float sum0 = 0.f, sum1 = 0.f;
#pragma unroll
        for (int n = 0; n < 8; n++) {
            s[n][0] = exp2f(s[n][0] - m0);
            s[n][1] = exp2f(s[n][1] - m0);
            s[n][2] = exp2f(s[n][2] - m1);
            s[n][3] = exp2f(s[n][3] - m1);
            sum0 += s[n][0] + s[n][1];
            sum1 += s[n][2] + s[n][3];
        }
        sum0 += __shfl_xor_sync(0xffffffffu, sum0, 1);
        sum0 += __shfl_xor_sync(0xffffffffu, sum0, 2);
        sum1 += __shfl_xor_sync(0xffffffffu, sum1, 1);
        sum1 += __shfl_xor_sync(0xffffffffu, sum1, 2);
        l0 = l0 * al0 + sum0;
        l1 = l1 * al1 + sum1;
#pragma unroll
        for (int n = 0; n < 16; n++) {
            o[n][0] *= al0; o[n][1] *= al0;
            o[n][2] *= al1; o[n][3] *= al1;
        }

        // ---- O += P V (register repack, 3 split passes) ----
#pragma unroll
        for (int kv = 0; kv < 4; kv++) {
            uint32_t pah[4], pal[4];
            split_pack(s[2 * kv][0],     s[2 * kv][1],     pah[0], pal[0]);
            split_pack(s[2 * kv][2],     s[2 * kv][3],     pah[1], pal[1]);
            split_pack(s[2 * kv + 1][0], s[2 * kv + 1][1], pah[2], pal[2]);
            split_pack(s[2 * kv + 1][2], s[2 * kv + 1][3], pah[3], pal[3]);
            const int vr = 16 * kv + v_rloc;
            const uint32_t vro = vr * 256;
            const int vsel = vr & 7;
#pragma unroll
            for (int i = 0; i < 8; i++) {
                const uint32_t ch = (uint32_t)(((2 * i + v_chh) ^ vsel) << 4);
                uint32_t vfh[4], vfl[4];
                ldsm_x4t(vfh, VhB + vro + ch);
                ldsm_x4t(vfl, VlB + vro + ch);
                mma16816(o[2 * i],     pah, &vfh[0]);
                mma16816(o[2 * i],     pah, &vfl[0]);
                mma16816(o[2 * i],     pal, &vfh[0]);
                mma16816(o[2 * i + 1], pah, &vfh[2]);
                mma16816(o[2 * i + 1], pah, &vfl[2]);
                mma16816(o[2 * i + 1], pal, &vfh[2]);
            }
        }

        __syncthreads();
        if (j + 2 < jmax) loadKV(j + 2, st);
    }

    // ---- epilogue: normalize, split bf16 hi/lo, write (b,t,c) ----
    const float inv0 = 1.f / l0, inv1 = 1.f / l1;
    const size_t r0base = ((size_t)b * TT + qg0) * CC + h * HD;
    const size_t r1base = ((size_t)b * TT + qg1) * CC + h * HD;
#pragma unroll
    for (int n = 0; n < 16; n++) {
        const int d = 8 * n + 2 * (lane & 3);
        uint32_t ph, pl;
        split_pack(o[n][0] * inv0, o[n][1] * inv0, ph, pl);
        *(uint32_t*)&outh[r0base + d] = ph;
        *(uint32_t*)&outl[r0base + d] = pl;
        split_pack(o[n][2] * inv1, o[n][3] * inv1, ph, pl);
        *(uint32_t*)&outh[r1base + d] = ph;
        *(uint32_t*)&outl[r1base + d] = pl;
    }
}

// ---------------------------------------------------------------------------
// Launcher
// ---------------------------------------------------------------------------
extern "C" void kernel_launch(void* const* d_in, const int* in_sizes, int n_in,
                              void* d_out, int out_size)
{
    const float* x    = (const float*)d_in[0];
    const float* mask = (const float*)d_in[1];
    const float* bq   = (const float*)d_in[3];
    const float* bk   = (const float*)d_in[5];
    const float* bv   = (const float*)d_in[7];
    const float* bp   = (const float*)d_in[9];
    const float* W[4] = {(const float*)d_in[2], (const float*)d_in[4],
                         (const float*)d_in[6], (const float*)d_in[8]};
    float* out = (float*)d_out;

    __nv_bfloat16 *xh, *xl, *ath, *atl, *wh, *wl;
    __nv_bfloat16 *qh, *ql, *kh, *kl, *vh, *vl;
    cudaGetSymbolAddress((void**)&xh,  g_xh);
    cudaGetSymbolAddress((void**)&xl,  g_xl);
    cudaGetSymbolAddress((void**)&ath, g_ath);
    cudaGetSymbolAddress((void**)&atl, g_atl);
    cudaGetSymbolAddress((void**)&wh,  g_wh);
    cudaGetSymbolAddress((void**)&wl,  g_wl);
    cudaGetSymbolAddress((void**)&qh,  g_qh);
    cudaGetSymbolAddress((void**)&ql,  g_ql);
    cudaGetSymbolAddress((void**)&kh,  g_kh);
    cudaGetSymbolAddress((void**)&kl,  g_kl);
    cudaGetSymbolAddress((void**)&vh,  g_vh);
    cudaGetSymbolAddress((void**)&vl,  g_vl);

    cudaFuncSetAttribute(gemm_tc_kernel,
                         cudaFuncAttributeMaxDynamicSharedMemorySize, GEMM_SMEM);
    cudaFuncSetAttribute(attn_tc_kernel,
                         cudaFuncAttributeMaxDynamicSharedMemorySize, ATT_SMEM);

    // 1. split x and weights into bf16 hi/lo
    {
        const int n4x = (BB * TT * CC) / 4;
        split_kernel<<<(n4x + 255) / 256, 256>>>(x, xh, xl, n4x);
        const int n4w = (CC * CC) / 4;
        for (int i = 0; i < 4; i++)
            split_kernel<<<(n4w + 255) / 256, 256>>>(
                W[i], wh + (size_t)i * CC * CC, wl + (size_t)i * CC * CC, n4w);
    }

    const dim3 gg(CC / BN, MROWS / BM);   // (16, 64)

    // 2. QKV projections -> bf16 hi/lo head layout (Q pre-scaled for exp2 domain)
    gemm_tc_kernel<<<gg, 256, GEMM_SMEM>>>(xh, xl, wh + 0 * (size_t)CC * CC,
        wl + 0 * (size_t)CC * CC, bq, QSCALE, nullptr, qh, ql, 1);
    gemm_tc_kernel<<<gg, 256, GEMM_SMEM>>>(xh, xl, wh + 1 * (size_t)CC * CC,
        wl + 1 * (size_t)CC * CC, bk, 1.0f, nullptr, kh, kl, 1);
    gemm_tc_kernel<<<gg, 256, GEMM_SMEM>>>(xh, xl, wh + 2 * (size_t)CC * CC,
        wl + 2 * (size_t)CC * CC, bv, 1.0f, nullptr, vh, vl, 1);

    // 3. flash attention -> bf16 hi/lo (b,t,c)
    attn_tc_kernel<<<dim3(TT / 128, BB * NH), 256, ATT_SMEM>>>(
        qh, ql, kh, kl, vh, vl, mask, ath, atl);

    // 4. output projection -> fp32 out
    gemm_tc_kernel<<<gg, 256, GEMM_SMEM>>>(ath, atl, wh + 3 * (size_t)CC * CC,
        wl + 3 * (size_t)CC * CC, bp, 1.0f, out, nullptr, nullptr, 0);
}

// round 10
// speedup vs baseline: 8.3740x; 1.4471x over previous
#include <cuda_runtime.h>
#include <cuda_fp16.h>
#include <math.h>
#include <stdint.h>
#include <stddef.h>

// Problem constants
#define BB   4
#define TT   2048
#define CC   2048
#define NH   16
#define HD   128
#define MROWS (BB * TT)          // 8192
#define LOG2E 1.4426950408889634f
#define QSCALE 0.12751743502016435f   // (1/sqrt(128)) * log2(e)

// ---------------------------------------------------------------------------
// Scratch (device globals)
// ---------------------------------------------------------------------------
__device__ __half g_xh[BB * TT * CC];      // x split hi (fp16)
__device__ __half g_xl[BB * TT * CC];      // x split lo
__device__ __half g_ath[BB * TT * CC];     // attention out split hi
__device__ __half g_atl[BB * TT * CC];     // attention out split lo
__device__ __half g_w[4][CC * CC];         // weights, single fp16
__device__ __half g_qh[BB * NH * TT * HD]; // (b,h,t,d) Q split hi
__device__ __half g_ql[BB * NH * TT * HD]; // Q split lo
__device__ __half g_kh[BB * NH * TT * HD]; // K single fp16
__device__ __half g_vh[BB * NH * TT * HD]; // V single fp16

// ---------------------------------------------------------------------------
// Helpers
// ---------------------------------------------------------------------------
__device__ __forceinline__ uint32_t smem_u32(const void* p) {
    uint32_t a;
    asm("{ .reg .u64 t; cvta.to.shared.u64 t, %1; cvt.u32.u64 %0, t; }"
        : "=r"(a) : "l"(p));
    return a;
}
__device__ __forceinline__ void cp16(uint32_t dst, const void* src) {
    asm volatile("cp.async.cg.shared.global [%0], [%1], 16;"
                 :: "r"(dst), "l"(src) : "memory");
}
__device__ __forceinline__ void ldsm_x4(uint32_t* r, uint32_t addr) {
    asm volatile("ldmatrix.sync.aligned.m8n8.x4.shared.b16 {%0,%1,%2,%3}, [%4];"
        : "=r"(r[0]), "=r"(r[1]), "=r"(r[2]), "=r"(r[3]) : "r"(addr));
}
__device__ __forceinline__ void ldsm_x4t(uint32_t* r, uint32_t addr) {
    asm volatile("ldmatrix.sync.aligned.m8n8.x4.trans.shared.b16 {%0,%1,%2,%3}, [%4];"
        : "=r"(r[0]), "=r"(r[1]), "=r"(r[2]), "=r"(r[3]) : "r"(addr));
}
__device__ __forceinline__ void ldsm_x2(uint32_t* r, uint32_t addr) {
    asm volatile("ldmatrix.sync.aligned.m8n8.x2.shared.b16 {%0,%1}, [%2];"
        : "=r"(r[0]), "=r"(r[1]) : "r"(addr));
}
// fp16 MMA m16n8k16, fp32 accumulate
__device__ __forceinline__ void mma16816(float* c, const uint32_t* a, const uint32_t* b) {
    asm volatile("mma.sync.aligned.m16n8k16.row.col.f32.f16.f16.f32 "
        "{%0,%1,%2,%3}, {%4,%5,%6,%7}, {%8,%9}, {%0,%1,%2,%3};"
        : "+f"(c[0]), "+f"(c[1]), "+f"(c[2]), "+f"(c[3])
        : "r"(a[0]), "r"(a[1]), "r"(a[2]), "r"(a[3]), "r"(b[0]), "r"(b[1]));
}
// pack (a,b) -> fp16x2 hi word + lo word (a in low half)
__device__ __forceinline__ void split_pack(float a, float b, uint32_t& h, uint32_t& l) {
    __half ah = __float2half_rn(a);
    __half bh = __float2half_rn(b);
    __half2 hh; hh.x = ah; hh.y = bh;
    h = *(uint32_t*)&hh;
    __half2 ll;
    ll.x = __float2half_rn(a - __half2float(ah));
    ll.y = __float2half_rn(b - __half2float(bh));
    l = *(uint32_t*)&ll;
}
__device__ __forceinline__ uint32_t pack_h2(float a, float b) {
    __half2 hh; hh.x = __float2half_rn(a); hh.y = __float2half_rn(b);
    return *(uint32_t*)&hh;
}

// ---------------------------------------------------------------------------
// fp32 -> fp16 hi/lo split
// ---------------------------------------------------------------------------
__global__ void split_kernel(const float* __restrict__ in,
                             __half* __restrict__ hi,
                             __half* __restrict__ lo, int n4)
{
    int i = blockIdx.x * blockDim.x + threadIdx.x;
    if (i >= n4) return;
    float4 v = ((const float4*)in)[i];
    float f[4] = {v.x, v.y, v.z, v.w};
    __align__(8) __half h[4];
    __align__(8) __half l[4];
#pragma unroll
    for (int j = 0; j < 4; j++) {
        h[j] = __float2half_rn(f[j]);
        l[j] = __float2half_rn(f[j] - __half2float(h[j]));
    }
    ((uint2*)hi)[i] = *(uint2*)h;
    ((uint2*)lo)[i] = *(uint2*)l;
}

// fp32 -> fp16 single convert
__global__ void conv_kernel(const float* __restrict__ in,
                            __half* __restrict__ out, int n4)
{
    int i = blockIdx.x * blockDim.x + threadIdx.x;
    if (i >= n4) return;
    float4 v = ((const float4*)in)[i];
    __align__(8) __half h[4];
    h[0] = __float2half_rn(v.x); h[1] = __float2half_rn(v.y);
    h[2] = __float2half_rn(v.z); h[3] = __float2half_rn(v.w);
    ((uint2*)out)[i] = *(uint2*)h;
}

// ---------------------------------------------------------------------------
// 2-pass fp16 tensor-core GEMM: out[i][j] = (sum_k A[i][k]*W[j][k] + bias[j])*escale
// A split (Ah+Al exact), W single fp16. CTA tile 128x128, BK=64,
// 4-stage cp.async pipeline, 8 warps (64x32 each).
// mode 0: fp32 flat out. mode 1: split fp16 head layout. mode 2: single fp16 head layout.
// ---------------------------------------------------------------------------
#define BM 128
#define BN 128
#define BK 64
#define NSTG 4
#define KCH (CC / BK)                 // 32
#define TILE_B 16384                  // 128 rows x 128 bytes
#define STG_B (3 * TILE_B)            // Ah, Al, W
static constexpr unsigned GEMM_SMEM = NSTG * STG_B;   // 196608

__global__ __launch_bounds__(256, 1)
void gemm_tc_kernel(const __half* __restrict__ Ah,
                    const __half* __restrict__ Al,
                    const __half* __restrict__ Wh,
                    const float* __restrict__ bias, float escale,
                    float* __restrict__ outf,
                    __half* __restrict__ outh,
                    __half* __restrict__ outl,
                    int mode)
{
    extern __shared__ char smem[];
    const uint32_t sb = smem_u32(smem);
    const int tid  = threadIdx.x;
    const int lane = tid & 31;
    const int wid  = tid >> 5;
    const int wr   = wid >> 2;
    const int wc   = wid & 3;
    const int bx = blockIdx.x, by = blockIdx.y;

    const __half* srcs[3] = {
        Ah + (size_t)by * BM * CC,
        Al + (size_t)by * BM * CC,
        Wh + (size_t)bx * BN * CC
    };

    auto load_stage = [&](int stg, int kc) {
        const uint32_t base = sb + stg * STG_B;
#pragma unroll
        for (int ti = 0; ti < 3; ti++) {
            const __half* src = srcs[ti];
            const uint32_t tb = base + ti * TILE_B;
#pragma unroll
            for (int i = 0; i < 4; i++) {
                const int idx = tid + i * 256;
                const int row = idx >> 3;
                const int ch  = idx & 7;
                const uint32_t dst = tb + row * 128 + ((ch ^ (row & 7)) << 4);
                cp16(dst, src + (size_t)row * CC + kc + ch * 8);
            }
        }
        asm volatile("cp.async.commit_group;" ::: "memory");
    };

    const int a_lr = lane & 15;
    const int a_hk = lane >> 4;
    uint32_t a_off[4]; int a_sel[4];
#pragma unroll
    for (int mt = 0; mt < 4; mt++) {
        const int r = wr * 64 + mt * 16 + a_lr;
        a_off[mt] = r * 128;
        a_sel[mt] = r & 7;
    }
    const int b_lr = lane & 7;
    const int b_hk = (lane >> 3) & 1;
    uint32_t b_off[4]; int b_sel[4];
#pragma unroll
    for (int nt = 0; nt < 4; nt++) {
        const int r = wc * 32 + nt * 8 + b_lr;
        b_off[nt] = r * 128;
        b_sel[nt] = r & 7;
    }

    float c[4][4][4];
#pragma unroll
    for (int mt = 0; mt < 4; mt++)
#pragma unroll
        for (int nt = 0; nt < 4; nt++)
#pragma unroll
            for (int i = 0; i < 4; i++) c[mt][nt][i] = 0.f;

    load_stage(0, 0);
    load_stage(1, BK);
    load_stage(2, 2 * BK);

    for (int chk = 0; chk < KCH; chk++) {
        const int rem = KCH - 1 - chk;
        if (rem >= 2)      asm volatile("cp.async.wait_group 2;" ::: "memory");
        else if (rem == 1) asm volatile("cp.async.wait_group 1;" ::: "memory");
        else               asm volatile("cp.async.wait_group 0;" ::: "memory");
        __syncthreads();

        const uint32_t base = sb + (chk % NSTG) * STG_B;
#pragma unroll
        for (int ks = 0; ks < 4; ks++) {
            uint32_t ah[4][4], al[4][4], bh[4][2];
            const int ca = ks * 2 + a_hk;
            const int cb = ks * 2 + b_hk;
#pragma unroll
            for (int mt = 0; mt < 4; mt++) {
                const uint32_t sw = (uint32_t)((ca ^ a_sel[mt]) << 4);
                ldsm_x4(ah[mt], base + a_off[mt] + sw);
                ldsm_x4(al[mt], base + TILE_B + a_off[mt] + sw);
            }
#pragma unroll
            for (int nt = 0; nt < 4; nt++) {
                const uint32_t sw = (uint32_t)((cb ^ b_sel[nt]) << 4);
                ldsm_x2(bh[nt], base + 2 * TILE_B + b_off[nt] + sw);
            }
#pragma unroll
            for (int mt = 0; mt < 4; mt++)
#pragma unroll
                for (int nt = 0; nt < 4; nt++) {
                    mma16816(c[mt][nt], ah[mt], bh[nt]);
                    mma16816(c[mt][nt], al[mt], bh[nt]);
                }
        }

        if (chk + 3 < KCH) load_stage((chk + 3) % NSTG, (chk + 3) * BK);
    }

    // ---- epilogue ----
    const int t4 = lane >> 2;
    const int t2 = (lane & 3) * 2;
#pragma unroll
    for (int mt = 0; mt < 4; mt++) {
        const int r0 = by * BM + wr * 64 + mt * 16 + t4;
        const int r1 = r0 + 8;
#pragma unroll
        for (int nt = 0; nt < 4; nt++) {
            const int col = bx * BN + wc * 32 + nt * 8 + t2;
            const float bi0 = bias[col], bi1 = bias[col + 1];
            float v00 = (c[mt][nt][0] + bi0) * escale;
            float v01 = (c[mt][nt][1] + bi1) * escale;
            float v10 = (c[mt][nt][2] + bi0) * escale;
            float v11 = (c[mt][nt][3] + bi1) * escale;
            if (mode == 0) {
                float2 v0 = {v00, v01}, v1 = {v10, v11};
                *(float2*)(outf + (size_t)r0 * CC + col) = v0;
                *(float2*)(outf + (size_t)r1 * CC + col) = v1;
            } else {
                const int d = col & 127;               // head = bx
                const int b0 = r0 >> 11, t0 = r0 & 2047;
                const int b1 = r1 >> 11, t1 = r1 & 2047;
                const size_t i0 = (((size_t)(b0 * NH + bx)) * TT + t0) * HD + d;
                const size_t i1 = (((size_t)(b1 * NH + bx)) * TT + t1) * HD + d;
                if (mode == 1) {
                    uint32_t ph, pl;
                    split_pack(v00, v01, ph, pl);
                    *(uint32_t*)&outh[i0] = ph; *(uint32_t*)&outl[i0] = pl;
                    split_pack(v10, v11, ph, pl);
                    *(uint32_t*)&outh[i1] = ph; *(uint32_t*)&outl[i1] = pl;
                } else {
                    *(uint32_t*)&outh[i0] = pack_h2(v00, v01);
                    *(uint32_t*)&outh[i1] = pack_h2(v10, v11);
                }
            }
        }
    }
}

// ---------------------------------------------------------------------------
// Tensor-core flash attention, fp16 2-pass, exp2 domain.
// Grid: (T/128, B*H). 256 threads = 8 warps x 16 query rows.
// Q split (exact), K single, P split (exact), V single. KV tiles of 64,
// double-buffered cp.async.
// Smem: Qh[0:32K], Ql[32K:64K], stage s at 64K + 32K*s: {K:0, V:16K}.
// Rows 256B, 16B-chunk XOR swizzle.
// ---------------------------------------------------------------------------
static constexpr unsigned ATT_SMEM = 131072;

__global__ __launch_bounds__(256, 1)
void attn_tc_kernel(const __half* __restrict__ qh, const __half* __restrict__ ql,
                    const __half* __restrict__ kh, const __half* __restrict__ vh,
                    const float* __restrict__ mask,
                    __half* __restrict__ outh, __half* __restrict__ outl)
{
    extern __shared__ char smem[];
    const uint32_t sb = smem_u32(smem);
    const int tid = threadIdx.x, lane = tid & 31, warp = tid >> 5;
    const int qb = gridDim.x - 1 - blockIdx.x;     // long CTAs first
    const int bh = blockIdx.y;
    const int b = bh >> 4, h = bh & 15;
    const int q0 = qb * 128;
    const int jmax = 2 * qb + 2;
    const size_t bhoff = (size_t)bh * TT * HD;

    // ---- Q tile load (hi + lo) ----
    {
        const __half* s0 = qh + bhoff + (size_t)q0 * HD;
        const __half* s1 = ql + bhoff + (size_t)q0 * HD;
#pragma unroll
        for (int i = 0; i < 8; i++) {
            const int idx = tid + i * 256;          // 2048 chunks per matrix
            const int r = idx >> 4, ch = idx & 15;
            const uint32_t off = r * 256 + ((ch ^ (r & 7)) << 4);
            cp16(sb + off,         s0 + (size_t)r * HD + ch * 8);
            cp16(sb + 32768 + off, s1 + (size_t)r * HD + ch * 8);
        }
        asm volatile("cp.async.commit_group;" ::: "memory");
    }

    auto loadKV = [&](int j, int st) {
        const uint32_t base = sb + 65536 + st * 32768;
        const int kv0 = j * 64;
        const __half* srcs[2] = {
            kh + bhoff + (size_t)kv0 * HD, vh + bhoff + (size_t)kv0 * HD };
#pragma unroll
        for (int i = 0; i < 8; i++) {
            const int idx = tid + i * 256;          // 2048 chunks
            const int mat = idx >> 10, r = (idx >> 4) & 63, ch = idx & 15;
            cp16(base + mat * 16384 + r * 256 + ((ch ^ (r & 7)) << 4),
                 srcs[mat] + (size_t)r * HD + ch * 8);
        }
        asm volatile("cp.async.commit_group;" ::: "memory");
    };

    loadKV(0, 0);
    loadKV(1, 1);

    float o[16][4];
#pragma unroll
    for (int n = 0; n < 16; n++)
#pragma unroll
        for (int i = 0; i < 4; i++) o[n][i] = 0.f;
    float m0 = -1e30f, m1 = -1e30f, l0 = 0.f, l1 = 0.f;

    // ldmatrix lane addressing
    const int qrow  = warp * 16 + (lane & 15);
    const uint32_t a_base = qrow * 256;
    const int a_sel = qrow & 7;
    const int a_kh  = lane >> 4;
    const int kb_rloc = ((lane >> 4) << 3) + (lane & 7);   // K (QK B-operand)
    const int kb_ch   = (lane >> 3) & 1;
    const int v_rloc  = lane & 15;                          // V (PV B-operand, trans)
    const int v_chh   = lane >> 4;

    const int qg0 = q0 + warp * 16 + (lane >> 2);
    const int qg1 = qg0 + 8;

    for (int j = 0; j < jmax; j++) {
        const int kv0 = j * 64;
        const int st = j & 1;
        if (j + 1 < jmax) asm volatile("cp.async.wait_group 1;" ::: "memory");
        else              asm volatile("cp.async.wait_group 0;" ::: "memory");
        __syncthreads();

        const uint32_t KB = sb + 65536 + st * 32768;
        const uint32_t VB = KB + 16384;

        // ---- S = Q K^T (2 split passes), 16x64 per warp ----
        float s[8][4];
#pragma unroll
        for (int n = 0; n < 8; n++)
#pragma unroll
            for (int i = 0; i < 4; i++) s[n][i] = 0.f;

#pragma unroll
        for (int ks = 0; ks < 8; ks++) {
            uint32_t qfh[4], qfl[4];
            const uint32_t ca = (uint32_t)(((2 * ks + a_kh) ^ a_sel) << 4);
            ldsm_x4(qfh, sb + a_base + ca);
            ldsm_x4(qfl, sb + 32768 + a_base + ca);
            uint32_t kf[16];
#pragma unroll
            for (int i = 0; i < 4; i++) {
                const int r = 16 * i + kb_rloc;
                const uint32_t off = r * 256 + (((2 * ks + kb_ch) ^ (r & 7)) << 4);
                ldsm_x4(&kf[4 * i], KB + off);
            }
#pragma unroll
            for (int n = 0; n < 8; n++) {
                mma16816(s[n], qfh, &kf[2 * n]);
                mma16816(s[n], qfl, &kf[2 * n]);
            }
        }

        // ---- mask + causal ----
        const bool need_mask = (j >= 2 * qb);
#pragma unroll
        for (int n = 0; n < 8; n++) {
            const int kg = kv0 + 8 * n + 2 * (lane & 3);
            const float2 mv = *(const float2*)&mask[b * TT + kg];
            const float am0 = mv.x * LOG2E, am1 = mv.y * LOG2E;
            s[n][0] += am0; s[n][1] += am1;
            s[n][2] += am0; s[n][3] += am1;
            if (need_mask) {
                if (kg     > qg0) s[n][0] = -1e30f;
                if (kg + 1 > qg0) s[n][1] = -1e30f;
                if (kg     > qg1) s[n][2] = -1e30f;
                if (kg + 1 > qg1) s[n][3] = -1e30f;
            }
        }

        // ---- online softmax (quad-local) ----
        float mx0 = m0, mx1 = m1;
#pragma unroll
        for (int n = 0; n < 8; n++) {
            mx0 = fmaxf(mx0, fmaxf(s[n][0], s[n][1]));
            mx1 = fmaxf(mx1, fmaxf(s[n][2], s[n][3]));
        }
        mx0 = fmaxf(mx0, __shfl_xor_sync(0xffffffffu, mx0, 1));
        mx0 = fmaxf(mx0, __shfl_xor_sync(0xffffffffu, mx0, 2));
        mx1 = fmaxf(mx1, __shfl_xor_sync(0xffffffffu, mx1, 1));
        mx1 = fmaxf(mx1, __shfl_xor_sync(0xffffffffu, mx1, 2));
        const float al0 = exp2f(m0 - mx0);
        const float al1 = exp2f(m1 - mx1);
        m0 = mx0; m1 = mx1;
        float sum0 = 0.f, sum1 = 0.f;
#pragma unroll
        for (int n = 0; n < 8; n++) {
            s[n][0] = exp2f(s[n][0] - m0);
            s[n][1] = exp2f(s[n][1] - m0);
            s[n][2] = exp2f(s[n][2] - m1);
            s[n][3] = exp2f(s[n][3] - m1);
            sum0 += s[n][0] + s[n][1];
            sum1 += s[n][2] + s[n][3];
        }
        sum0 += __shfl_xor_sync(0xffffffffu, sum0, 1);
        sum0 += __shfl_xor_sync(0xffffffffu, sum0, 2);
        sum1 += __shfl_xor_sync(0xffffffffu, sum1, 1);
        sum1 += __shfl_xor_sync(0xffffffffu, sum1, 2);
        l0 = l0 * al0 + sum0;
        l1 = l1 * al1 + sum1;
#pragma unroll
        for (int n = 0; n < 16; n++) {
            o[n][0] *= al0; o[n][1] *= al0;
            o[n][2] *= al1; o[n][3] *= al1;
        }

        // ---- O += P V (register repack, P split exact, V single) ----
#pragma unroll
        for (int kv = 0; kv < 4; kv++) {
            uint32_t pah[4], pal[4];
            split_pack(s[2 * kv][0],     s[2 * kv][1],     pah[0], pal[0]);
            split_pack(s[2 * kv][2],     s[2 * kv][3],     pah[1], pal[1]);
            split_pack(s[2 * kv + 1][0], s[2 * kv + 1][1], pah[2], pal[2]);
            split_pack(s[2 * kv + 1][2], s[2 * kv + 1][3], pah[3], pal[3]);
            const int vr = 16 * kv + v_rloc;
            const uint32_t vro = vr * 256;
            const int vsel = vr & 7;
#pragma unroll
            for (int i = 0; i < 8; i++) {
                const uint32_t ch = (uint32_t)(((2 * i + v_chh) ^ vsel) << 4);
                uint32_t vf[4];
                ldsm_x4t(vf, VB + vro + ch);
                mma16816(o[2 * i],     pah, &vf[0]);
                mma16816(o[2 * i],     pal, &vf[0]);
                mma16816(o[2 * i + 1], pah, &vf[2]);
                mma16816(o[2 * i + 1], pal, &vf[2]);
            }
        }

        __syncthreads();
        if (j + 2 < jmax) loadKV(j + 2, st);
    }

    // ---- epilogue: normalize, split fp16 hi/lo, write (b,t,c) ----
    const float inv0 = 1.f / l0, inv1 = 1.f / l1;
    const size_t r0base = ((size_t)b * TT + qg0) * CC + h * HD;
    const size_t r1base = ((size_t)b * TT + qg1) * CC + h * HD;
#pragma unroll
    for (int n = 0; n < 16; n++) {
        const int d = 8 * n + 2 * (lane & 3);
        uint32_t ph, pl;
        split_pack(o[n][0] * inv0, o[n][1] * inv0, ph, pl);
        *(uint32_t*)&outh[r0base + d] = ph;
        *(uint32_t*)&outl[r0base + d] = pl;
        split_pack(o[n][2] * inv1, o[n][3] * inv1, ph, pl);
        *(uint32_t*)&outh[r1base + d] = ph;
        *(uint32_t*)&outl[r1base + d] = pl;
    }
}

// ---------------------------------------------------------------------------
// Launcher
// ---------------------------------------------------------------------------
extern "C" void kernel_launch(void* const* d_in, const int* in_sizes, int n_in,
                              void* d_out, int out_size)
{
    const float* x    = (const float*)d_in[0];
    const float* mask = (const float*)d_in[1];
    const float* bq   = (const float*)d_in[3];
    const float* bk   = (const float*)d_in[5];
    const float* bv   = (const float*)d_in[7];
    const float* bp   = (const float*)d_in[9];
    const float* W[4] = {(const float*)d_in[2], (const float*)d_in[4],
                         (const float*)d_in[6], (const float*)d_in[8]};
    float* out = (float*)d_out;

    __half *xh, *xl, *ath, *atl, *w, *qh, *ql, *kh, *vhp;
    cudaGetSymbolAddress((void**)&xh,  g_xh);
    cudaGetSymbolAddress((void**)&xl,  g_xl);
    cudaGetSymbolAddress((void**)&ath, g_ath);
    cudaGetSymbolAddress((void**)&atl, g_atl);
    cudaGetSymbolAddress((void**)&w,   g_w);
    cudaGetSymbolAddress((void**)&qh,  g_qh);
    cudaGetSymbolAddress((void**)&ql,  g_ql);
    cudaGetSymbolAddress((void**)&kh,  g_kh);
    cudaGetSymbolAddress((void**)&vhp, g_vh);

    cudaFuncSetAttribute(gemm_tc_kernel,
                         cudaFuncAttributeMaxDynamicSharedMemorySize, GEMM_SMEM);
    cudaFuncSetAttribute(attn_tc_kernel,
                         cudaFuncAttributeMaxDynamicSharedMemorySize, ATT_SMEM);

    // 1. split x to fp16 hi/lo; convert weights to fp16
    {
        const int n4x = (BB * TT * CC) / 4;
        split_kernel<<<(n4x + 255) / 256, 256>>>(x, xh, xl, n4x);
        const int n4w = (CC * CC) / 4;
        for (int i = 0; i < 4; i++)
            conv_kernel<<<(n4w + 255) / 256, 256>>>(W[i], w + (size_t)i * CC * CC, n4w);
    }

    const dim3 gg(CC / BN, MROWS / BM);   // (16, 64)

    // 2. QKV projections (Q split + pre-scaled for exp2 domain; K,V single fp16)
    gemm_tc_kernel<<<gg, 256, GEMM_SMEM>>>(xh, xl, w + 0 * (size_t)CC * CC,
        bq, QSCALE, nullptr, qh, ql, 1);
    gemm_tc_kernel<<<gg, 256, GEMM_SMEM>>>(xh, xl, w + 1 * (size_t)CC * CC,
        bk, 1.0f, nullptr, kh, nullptr, 2);
    gemm_tc_kernel<<<gg, 256, GEMM_SMEM>>>(xh, xl, w + 2 * (size_t)CC * CC,
        bv, 1.0f, nullptr, vhp, nullptr, 2);

    // 3. flash attention -> fp16 hi/lo (b,t,c)
    attn_tc_kernel<<<dim3(TT / 128, BB * NH), 256, ATT_SMEM>>>(
        qh, ql, kh, vhp, mask, ath, atl);

    // 4. output projection -> fp32 out
    gemm_tc_kernel<<<gg, 256, GEMM_SMEM>>>(ath, atl, w + 3 * (size_t)CC * CC,
        bp, 1.0f, out, nullptr, nullptr, 0);
}

// round 11
// speedup vs baseline: 9.1584x; 1.0937x over previous
#include <cuda_runtime.h>
#include <cuda_fp16.h>
#include <math.h>
#include <stdint.h>
#include <stddef.h>

// Problem constants
#define BB   4
#define TT   2048
#define CC   2048
#define NH   16
#define HD   128
#define MROWS (BB * TT)          // 8192
#define LOG2E 1.4426950408889634f
#define QSCALE 0.12751743502016435f   // (1/sqrt(128)) * log2(e)

// ---------------------------------------------------------------------------
// Scratch (device globals)
// ---------------------------------------------------------------------------
__device__ __half g_xh[BB * TT * CC];      // x split hi (fp16)
__device__ __half g_xl[BB * TT * CC];      // x split lo
__device__ __half g_at[BB * TT * CC];      // attention out, single fp16
__device__ __half g_w[4][CC * CC];         // weights, single fp16
__device__ __half g_qh[BB * NH * TT * HD]; // (b,h,t,d) Q split hi
__device__ __half g_ql[BB * NH * TT * HD]; // Q split lo
__device__ __half g_kh[BB * NH * TT * HD]; // K single fp16
__device__ __half g_vh[BB * NH * TT * HD]; // V single fp16

// ---------------------------------------------------------------------------
// Helpers
// ---------------------------------------------------------------------------
__device__ __forceinline__ uint32_t smem_u32(const void* p) {
    uint32_t a;
    asm("{ .reg .u64 t; cvta.to.shared.u64 t, %1; cvt.u32.u64 %0, t; }"
        : "=r"(a) : "l"(p));
    return a;
}
__device__ __forceinline__ void cp16(uint32_t dst, const void* src) {
    asm volatile("cp.async.cg.shared.global [%0], [%1], 16;"
                 :: "r"(dst), "l"(src) : "memory");
}
__device__ __forceinline__ void ldsm_x4(uint32_t* r, uint32_t addr) {
    asm volatile("ldmatrix.sync.aligned.m8n8.x4.shared.b16 {%0,%1,%2,%3}, [%4];"
        : "=r"(r[0]), "=r"(r[1]), "=r"(r[2]), "=r"(r[3]) : "r"(addr));
}
__device__ __forceinline__ void ldsm_x4t(uint32_t* r, uint32_t addr) {
    asm volatile("ldmatrix.sync.aligned.m8n8.x4.trans.shared.b16 {%0,%1,%2,%3}, [%4];"
        : "=r"(r[0]), "=r"(r[1]), "=r"(r[2]), "=r"(r[3]) : "r"(addr));
}
// fp16 MMA m16n8k16, fp32 accumulate
__device__ __forceinline__ void mma16816(float* c, const uint32_t* a, const uint32_t* b) {
    asm volatile("mma.sync.aligned.m16n8k16.row.col.f32.f16.f16.f32 "
        "{%0,%1,%2,%3}, {%4,%5,%6,%7}, {%8,%9}, {%0,%1,%2,%3};"
        : "+f"(c[0]), "+f"(c[1]), "+f"(c[2]), "+f"(c[3])
        : "r"(a[0]), "r"(a[1]), "r"(a[2]), "r"(a[3]), "r"(b[0]), "r"(b[1]));
}
// pack (a,b) -> fp16x2 hi word + lo word (a in low half)
__device__ __forceinline__ void split_pack(float a, float b, uint32_t& h, uint32_t& l) {
    __half ah = __float2half_rn(a);
    __half bh = __float2half_rn(b);
    __half2 hh; hh.x = ah; hh.y = bh;
    h = *(uint32_t*)&hh;
    __half2 ll;
    ll.x = __float2half_rn(a - __half2float(ah));
    ll.y = __float2half_rn(b - __half2float(bh));
    l = *(uint32_t*)&ll;
}
__device__ __forceinline__ uint32_t pack_h2(float a, float b) {
    __half2 hh; hh.x = __float2half_rn(a); hh.y = __float2half_rn(b);
    return *(uint32_t*)&hh;
}

// ---------------------------------------------------------------------------
// fp32 -> fp16 hi/lo split
// ---------------------------------------------------------------------------
__global__ void split_kernel(const float* __restrict__ in,
                             __half* __restrict__ hi,
                             __half* __restrict__ lo, int n4)
{
    int i = blockIdx.x * blockDim.x + threadIdx.x;
    if (i >= n4) return;
    float4 v = ((const float4*)in)[i];
    float f[4] = {v.x, v.y, v.z, v.w};
    __align__(8) __half h[4];
    __align__(8) __half l[4];
#pragma unroll
    for (int j = 0; j < 4; j++) {
        h[j] = __float2half_rn(f[j]);
        l[j] = __float2half_rn(f[j] - __half2float(h[j]));
    }
    ((uint2*)hi)[i] = *(uint2*)h;
    ((uint2*)lo)[i] = *(uint2*)l;
}

// fp32 -> fp16 single convert
__global__ void conv_kernel(const float* __restrict__ in,
                            __half* __restrict__ out, int n4)
{
    int i = blockIdx.x * blockDim.x + threadIdx.x;
    if (i >= n4) return;
    float4 v = ((const float4*)in)[i];
    __align__(8) __half h[4];
    h[0] = __float2half_rn(v.x); h[1] = __float2half_rn(v.y);
    h[2] = __float2half_rn(v.z); h[3] = __float2half_rn(v.w);
    ((uint2*)out)[i] = *(uint2*)h;
}

// ---------------------------------------------------------------------------
// Common GEMM geometry
// ---------------------------------------------------------------------------
#define BM 128
#define BN 128
#define BK 64
#define KCH (CC / BK)                 // 32
#define TILE_B 16384                  // 128 rows x 128 bytes

// ---------------------------------------------------------------------------
// Fused QKV GEMM (2-pass split-fp16):
//   grid (48, 64); bx>>4 selects {Q,K,V}; bx&15 = head/N-tile.
//   out Q -> split hi/lo (pre-scaled QSCALE); K,V -> single fp16, head layout.
// ---------------------------------------------------------------------------
#define NSTG 4
#define STG_B (3 * TILE_B)            // Ah, Al, W
static constexpr unsigned GEMM_SMEM = NSTG * STG_B;   // 196608

__global__ __launch_bounds__(256, 1)
void gemm_qkv_kernel(const __half* __restrict__ Ah,
                     const __half* __restrict__ Al,
                     const __half* __restrict__ Wbase,
                     const float* __restrict__ bq,
                     const float* __restrict__ bk,
                     const float* __restrict__ bv,
                     __half* __restrict__ qh, __half* __restrict__ ql,
                     __half* __restrict__ kh, __half* __restrict__ vh)
{
    extern __shared__ char smem[];
    const uint32_t sb = smem_u32(smem);
    const int tid  = threadIdx.x;
    const int lane = tid & 31;
    const int wid  = tid >> 5;
    const int wr   = wid >> 2;
    const int wc   = wid & 3;
    const int bx = blockIdx.x, by = blockIdx.y;
    const int sel = bx >> 4;              // 0=Q, 1=K, 2=V
    const int hx  = bx & 15;              // head / N-tile

    const float* bias = (sel == 0) ? bq : (sel == 1) ? bk : bv;
    const float escale = (sel == 0) ? QSCALE : 1.0f;

    const __half* srcs[3] = {
        Ah + (size_t)by * BM * CC,
        Al + (size_t)by * BM * CC,
        Wbase + (size_t)sel * CC * CC + (size_t)hx * BN * CC
    };

    auto load_stage = [&](int stg, int kc) {
        const uint32_t base = sb + stg * STG_B;
#pragma unroll
        for (int ti = 0; ti < 3; ti++) {
            const __half* src = srcs[ti];
            const uint32_t tb = base + ti * TILE_B;
#pragma unroll
            for (int i = 0; i < 4; i++) {
                const int idx = tid + i * 256;
                const int row = idx >> 3;
                const int ch  = idx & 7;
                const uint32_t dst = tb + row * 128 + ((ch ^ (row & 7)) << 4);
                cp16(dst, src + (size_t)row * CC + kc + ch * 8);
            }
        }
        asm volatile("cp.async.commit_group;" ::: "memory");
    };

    // A-fragment addressing
    const int a_lr = lane & 15;
    const int a_hk = lane >> 4;
    uint32_t a_off[4]; int a_sel[4];
#pragma unroll
    for (int mt = 0; mt < 4; mt++) {
        const int r = wr * 64 + mt * 16 + a_lr;
        a_off[mt] = r * 128;
        a_sel[mt] = r & 7;
    }
    // B-fragment addressing (x4: two n8 tiles per load)
    const int b_rloc = ((lane >> 4) << 3) + (lane & 7);
    const int b_ch   = (lane >> 3) & 1;
    uint32_t b_off[2]; int b_sel2[2];
#pragma unroll
    for (int ntp = 0; ntp < 2; ntp++) {
        const int r = wc * 32 + ntp * 16 + b_rloc;
        b_off[ntp] = r * 128;
        b_sel2[ntp] = r & 7;
    }

    float c[4][4][4];
#pragma unroll
    for (int mt = 0; mt < 4; mt++)
#pragma unroll
        for (int nt = 0; nt < 4; nt++)
#pragma unroll
            for (int i = 0; i < 4; i++) c[mt][nt][i] = 0.f;

    load_stage(0, 0);
    load_stage(1, BK);
    load_stage(2, 2 * BK);

    for (int chk = 0; chk < KCH; chk++) {
        const int rem = KCH - 1 - chk;
        if (rem >= 2)      asm volatile("cp.async.wait_group 2;" ::: "memory");
        else if (rem == 1) asm volatile("cp.async.wait_group 1;" ::: "memory");
        else               asm volatile("cp.async.wait_group 0;" ::: "memory");
        __syncthreads();

        const uint32_t base = sb + (chk % NSTG) * STG_B;
#pragma unroll
        for (int ks = 0; ks < 4; ks++) {
            uint32_t ah[4][4], al[4][4], bf[2][4];
            const int ca = ks * 2 + a_hk;
            const int cb = ks * 2 + b_ch;
#pragma unroll
            for (int mt = 0; mt < 4; mt++) {
                const uint32_t sw = (uint32_t)((ca ^ a_sel[mt]) << 4);
                ldsm_x4(ah[mt], base + a_off[mt] + sw);
                ldsm_x4(al[mt], base + TILE_B + a_off[mt] + sw);
            }
#pragma unroll
            for (int ntp = 0; ntp < 2; ntp++) {
                const uint32_t sw = (uint32_t)((cb ^ b_sel2[ntp]) << 4);
                ldsm_x4(bf[ntp], base + 2 * TILE_B + b_off[ntp] + sw);
            }
#pragma unroll
            for (int mt = 0; mt < 4; mt++)
#pragma unroll
                for (int nt = 0; nt < 4; nt++) {
                    const uint32_t* bp = &bf[nt >> 1][(nt & 1) * 2];
                    mma16816(c[mt][nt], ah[mt], bp);
                    mma16816(c[mt][nt], al[mt], bp);
                }
        }

        if (chk + 3 < KCH) load_stage((chk + 3) % NSTG, (chk + 3) * BK);
    }

    // ---- epilogue (head layout) ----
    const int t4 = lane >> 2;
    const int t2 = (lane & 3) * 2;
#pragma unroll
    for (int mt = 0; mt < 4; mt++) {
        const int r0 = by * BM + wr * 64 + mt * 16 + t4;
        const int r1 = r0 + 8;
#pragma unroll
        for (int nt = 0; nt < 4; nt++) {
            const int col = hx * BN + wc * 32 + nt * 8 + t2;
            const float bi0 = bias[col], bi1 = bias[col + 1];
            const float v00 = (c[mt][nt][0] + bi0) * escale;
            const float v01 = (c[mt][nt][1] + bi1) * escale;
            const float v10 = (c[mt][nt][2] + bi0) * escale;
            const float v11 = (c[mt][nt][3] + bi1) * escale;
            const int d = col & 127;
            const int b0 = r0 >> 11, t0 = r0 & 2047;
            const int b1 = r1 >> 11, t1 = r1 & 2047;
            const size_t i0 = (((size_t)(b0 * NH + hx)) * TT + t0) * HD + d;
            const size_t i1 = (((size_t)(b1 * NH + hx)) * TT + t1) * HD + d;
            if (sel == 0) {
                uint32_t ph, pl;
                split_pack(v00, v01, ph, pl);
                *(uint32_t*)&qh[i0] = ph; *(uint32_t*)&ql[i0] = pl;
                split_pack(v10, v11, ph, pl);
                *(uint32_t*)&qh[i1] = ph; *(uint32_t*)&ql[i1] = pl;
            } else {
                __half* o = (sel == 1) ? kh : vh;
                *(uint32_t*)&o[i0] = pack_h2(v00, v01);
                *(uint32_t*)&o[i1] = pack_h2(v10, v11);
            }
        }
    }
}

// ---------------------------------------------------------------------------
// 1-pass fp16 GEMM (output projection): out = att @ Wp^T + bp, fp32 out.
// grid (16, 64). 4-stage pipeline, 32KB/stage.
// ---------------------------------------------------------------------------
#define P_NSTG 4
#define P_STG_B (2 * TILE_B)          // A, W
static constexpr unsigned GEMM1_SMEM = P_NSTG * P_STG_B;   // 131072

__global__ __launch_bounds__(256, 1)
void gemm1_tc_kernel(const __half* __restrict__ A,
                     const __half* __restrict__ W,
                     const float* __restrict__ bias,
                     float* __restrict__ out)
{
    extern __shared__ char smem[];
    const uint32_t sb = smem_u32(smem);
    const int tid  = threadIdx.x;
    const int lane = tid & 31;
    const int wid  = tid >> 5;
    const int wr   = wid >> 2;
    const int wc   = wid & 3;
    const int bx = blockIdx.x, by = blockIdx.y;

    const __half* srcs[2] = {
        A + (size_t)by * BM * CC,
        W + (size_t)bx * BN * CC
    };

    auto load_stage = [&](int stg, int kc) {
        const uint32_t base = sb + stg * P_STG_B;
#pragma unroll
        for (int ti = 0; ti < 2; ti++) {
            const __half* src = srcs[ti];
            const uint32_t tb = base + ti * TILE_B;
#pragma unroll
            for (int i = 0; i < 4; i++) {
                const int idx = tid + i * 256;
                const int row = idx >> 3;
                const int ch  = idx & 7;
                const uint32_t dst = tb + row * 128 + ((ch ^ (row & 7)) << 4);
                cp16(dst, src + (size_t)row * CC + kc + ch * 8);
            }
        }
        asm volatile("cp.async.commit_group;" ::: "memory");
    };

    const int a_lr = lane & 15;
    const int a_hk = lane >> 4;
    uint32_t a_off[4]; int a_sel[4];
#pragma unroll
    for (int mt = 0; mt < 4; mt++) {
        const int r = wr * 64 + mt * 16 + a_lr;
        a_off[mt] = r * 128;
        a_sel[mt] = r & 7;
    }
    const int b_rloc = ((lane >> 4) << 3) + (lane & 7);
    const int b_ch   = (lane >> 3) & 1;
    uint32_t b_off[2]; int b_sel2[2];
#pragma unroll
    for (int ntp = 0; ntp < 2; ntp++) {
        const int r = wc * 32 + ntp * 16 + b_rloc;
        b_off[ntp] = r * 128;
        b_sel2[ntp] = r & 7;
    }

    float c[4][4][4];
#pragma unroll
    for (int mt = 0; mt < 4; mt++)
#pragma unroll
        for (int nt = 0; nt < 4; nt++)
#pragma unroll
            for (int i = 0; i < 4; i++) c[mt][nt][i] = 0.f;

    load_stage(0, 0);
    load_stage(1, BK);
    load_stage(2, 2 * BK);

    for (int chk = 0; chk < KCH; chk++) {
        const int rem = KCH - 1 - chk;
        if (rem >= 2)      asm volatile("cp.async.wait_group 2;" ::: "memory");
        else if (rem == 1) asm volatile("cp.async.wait_group 1;" ::: "memory");
        else               asm volatile("cp.async.wait_group 0;" ::: "memory");
        __syncthreads();

        const uint32_t base = sb + (chk % P_NSTG) * P_STG_B;
#pragma unroll
        for (int ks = 0; ks < 4; ks++) {
            uint32_t ah[4][4], bf[2][4];
            const int ca = ks * 2 + a_hk;
            const int cb = ks * 2 + b_ch;
#pragma unroll
            for (int mt = 0; mt < 4; mt++)
                ldsm_x4(ah[mt], base + a_off[mt] + (uint32_t)(((ca ^ a_sel[mt])) << 4));
#pragma unroll
            for (int ntp = 0; ntp < 2; ntp++)
                ldsm_x4(bf[ntp], base + TILE_B + b_off[ntp] + (uint32_t)(((cb ^ b_sel2[ntp])) << 4));
#pragma unroll
            for (int mt = 0; mt < 4; mt++)
#pragma unroll
                for (int nt = 0; nt < 4; nt++)
                    mma16816(c[mt][nt], ah[mt], &bf[nt >> 1][(nt & 1) * 2]);
        }

        if (chk + 3 < KCH) load_stage((chk + 3) % P_NSTG, (chk + 3) * BK);
    }

    const int t4 = lane >> 2;
    const int t2 = (lane & 3) * 2;
#pragma unroll
    for (int mt = 0; mt < 4; mt++) {
        const int r0 = by * BM + wr * 64 + mt * 16 + t4;
        const int r1 = r0 + 8;
#pragma unroll
        for (int nt = 0; nt < 4; nt++) {
            const int col = bx * BN + wc * 32 + nt * 8 + t2;
            const float bi0 = bias[col], bi1 = bias[col + 1];
            float2 v0 = {c[mt][nt][0] + bi0, c[mt][nt][1] + bi1};
            float2 v1 = {c[mt][nt][2] + bi0, c[mt][nt][3] + bi1};
            *(float2*)(out + (size_t)r0 * CC + col) = v0;
            *(float2*)(out + (size_t)r1 * CC + col) = v1;
        }
    }
}

// ---------------------------------------------------------------------------
// Tensor-core flash attention, fp16, exp2 domain.
// Grid: (T/128, B*H). 256 threads = 8 warps x 16 query rows.
// Q split (exact), K single, P split (exact), V single. KV tiles of 64,
// double-buffered cp.async. Output: single fp16, (b,t,c) layout.
// Smem: Qh[0:32K], Ql[32K:64K], stage s at 64K + 32K*s: {K:0, V:16K}.
// ---------------------------------------------------------------------------
static constexpr unsigned ATT_SMEM = 131072;

__global__ __launch_bounds__(256, 1)
void attn_tc_kernel(const __half* __restrict__ qh, const __half* __restrict__ ql,
                    const __half* __restrict__ kh, const __half* __restrict__ vh,
                    const float* __restrict__ mask,
                    __half* __restrict__ outp)
{
    extern __shared__ char smem[];
    const uint32_t sb = smem_u32(smem);
    const int tid = threadIdx.x, lane = tid & 31, warp = tid >> 5;
    const int qb = gridDim.x - 1 - blockIdx.x;     // long CTAs first
    const int bh = blockIdx.y;
    const int b = bh >> 4, h = bh & 15;
    const int q0 = qb * 128;
    const int jmax = 2 * qb + 2;
    const size_t bhoff = (size_t)bh * TT * HD;

    // ---- Q tile load (hi + lo) ----
    {
        const __half* s0 = qh + bhoff + (size_t)q0 * HD;
        const __half* s1 = ql + bhoff + (size_t)q0 * HD;
#pragma unroll
        for (int i = 0; i < 8; i++) {
            const int idx = tid + i * 256;
            const int r = idx >> 4, ch = idx & 15;
            const uint32_t off = r * 256 + ((ch ^ (r & 7)) << 4);
            cp16(sb + off,         s0 + (size_t)r * HD + ch * 8);
            cp16(sb + 32768 + off, s1 + (size_t)r * HD + ch * 8);
        }
        asm volatile("cp.async.commit_group;" ::: "memory");
    }

    auto loadKV = [&](int j, int st) {
        const uint32_t base = sb + 65536 + st * 32768;
        const int kv0 = j * 64;
        const __half* srcs[2] = {
            kh + bhoff + (size_t)kv0 * HD, vh + bhoff + (size_t)kv0 * HD };
#pragma unroll
        for (int i = 0; i < 8; i++) {
            const int idx = tid + i * 256;
            const int mat = idx >> 10, r = (idx >> 4) & 63, ch = idx & 15;
            cp16(base + mat * 16384 + r * 256 + ((ch ^ (r & 7)) << 4),
                 srcs[mat] + (size_t)r * HD + ch * 8);
        }
        asm volatile("cp.async.commit_group;" ::: "memory");
    };

    loadKV(0, 0);
    loadKV(1, 1);

    float o[16][4];
#pragma unroll
    for (int n = 0; n < 16; n++)
#pragma unroll
        for (int i = 0; i < 4; i++) o[n][i] = 0.f;
    float m0 = -1e30f, m1 = -1e30f, l0 = 0.f, l1 = 0.f;

    const int qrow  = warp * 16 + (lane & 15);
    const uint32_t a_base = qrow * 256;
    const int a_sel = qrow & 7;
    const int a_kh  = lane >> 4;
    const int kb_rloc = ((lane >> 4) << 3) + (lane & 7);
    const int kb_ch   = (lane >> 3) & 1;
    const int v_rloc  = lane & 15;
    const int v_chh   = lane >> 4;

    const int qg0 = q0 + warp * 16 + (lane >> 2);
    const int qg1 = qg0 + 8;

    for (int j = 0; j < jmax; j++) {
        const int kv0 = j * 64;
        const int st = j & 1;
        if (j + 1 < jmax) asm volatile("cp.async.wait_group 1;" ::: "memory");
        else              asm volatile("cp.async.wait_group 0;" ::: "memory");
        __syncthreads();

        const uint32_t KB = sb + 65536 + st * 32768;
        const uint32_t VB = KB + 16384;

        // ---- S = Q K^T (2 split passes), 16x64 per warp ----
        float s[8][4];
#pragma unroll
        for (int n = 0; n < 8; n++)
#pragma unroll
            for (int i = 0; i < 4; i++) s[n][i] = 0.f;

#pragma unroll
        for (int ks = 0; ks < 8; ks++) {
            uint32_t qfh[4], qfl[4];
            const uint32_t ca = (uint32_t)(((2 * ks + a_kh) ^ a_sel) << 4);
            ldsm_x4(qfh, sb + a_base + ca);
            ldsm_x4(qfl, sb + 32768 + a_base + ca);
            uint32_t kf[16];
#pragma unroll
            for (int i = 0; i < 4; i++) {
                const int r = 16 * i + kb_rloc;
                const uint32_t off = r * 256 + (((2 * ks + kb_ch) ^ (r & 7)) << 4);
                ldsm_x4(&kf[4 * i], KB + off);
            }
#pragma unroll
            for (int n = 0; n < 8; n++) {
                mma16816(s[n], qfh, &kf[2 * n]);
                mma16816(s[n], qfl, &kf[2 * n]);
            }
        }

        // ---- mask + causal ----
        const bool need_mask = (j >= 2 * qb);
#pragma unroll
        for (int n = 0; n < 8; n++) {
            const int kg = kv0 + 8 * n + 2 * (lane & 3);
            const float2 mv = *(const float2*)&mask[b * TT + kg];
            const float am0 = mv.x * LOG2E, am1 = mv.y * LOG2E;
            s[n][0] += am0; s[n][1] += am1;
            s[n][2] += am0; s[n][3] += am1;
            if (need_mask) {
                if (kg     > qg0) s[n][0] = -1e30f;
                if (kg + 1 > qg0) s[n][1] = -1e30f;
                if (kg     > qg1) s[n][2] = -1e30f;
                if (kg + 1 > qg1) s[n][3] = -1e30f;
            }
        }

        // ---- online softmax (quad-local) ----
        float mx0 = m0, mx1 = m1;
#pragma unroll
        for (int n = 0; n < 8; n++) {
            mx0 = fmaxf(mx0, fmaxf(s[n][0], s[n][1]));
            mx1 = fmaxf(mx1, fmaxf(s[n][2], s[n][3]));
        }
        mx0 = fmaxf(mx0, __shfl_xor_sync(0xffffffffu, mx0, 1));
        mx0 = fmaxf(mx0, __shfl_xor_sync(0xffffffffu, mx0, 2));
        mx1 = fmaxf(mx1, __shfl_xor_sync(0xffffffffu, mx1, 1));
        mx1 = fmaxf(mx1, __shfl_xor_sync(0xffffffffu, mx1, 2));
        const float al0 = exp2f(m0 - mx0);
        const float al1 = exp2f(m1 - mx1);
        m0 = mx0; m1 = mx1;
        float sum0 = 0.f, sum1 = 0.f;
#pragma unroll
        for (int n = 0; n < 8; n++) {
            s[n][0] = exp2f(s[n][0] - m0);
            s[n][1] = exp2f(s[n][1] - m0);
            s[n][2] = exp2f(s[n][2] - m1);
            s[n][3] = exp2f(s[n][3] - m1);
            sum0 += s[n][0] + s[n][1];
            sum1 += s[n][2] + s[n][3];
        }
        sum0 += __shfl_xor_sync(0xffffffffu, sum0, 1);
        sum0 += __shfl_xor_sync(0xffffffffu, sum0, 2);
        sum1 += __shfl_xor_sync(0xffffffffu, sum1, 1);
        sum1 += __shfl_xor_sync(0xffffffffu, sum1, 2);
        l0 = l0 * al0 + sum0;
        l1 = l1 * al1 + sum1;
#pragma unroll
        for (int n = 0; n < 16; n++) {
            o[n][0] *= al0; o[n][1] *= al0;
            o[n][2] *= al1; o[n][3] *= al1;
        }

        // ---- O += P V (register repack, P split exact, V single) ----
#pragma unroll
        for (int kv = 0; kv < 4; kv++) {
            uint32_t pah[4], pal[4];
            split_pack(s[2 * kv][0],     s[2 * kv][1],     pah[0], pal[0]);
            split_pack(s[2 * kv][2],     s[2 * kv][3],     pah[1], pal[1]);
            split_pack(s[2 * kv + 1][0], s[2 * kv + 1][1], pah[2], pal[2]);
            split_pack(s[2 * kv + 1][2], s[2 * kv + 1][3], pah[3], pal[3]);
            const int vr = 16 * kv + v_rloc;
            const uint32_t vro = vr * 256;
            const int vsel = vr & 7;
#pragma unroll
            for (int i = 0; i < 8; i++) {
                const uint32_t ch = (uint32_t)(((2 * i + v_chh) ^ vsel) << 4);
                uint32_t vf[4];
                ldsm_x4t(vf, VB + vro + ch);
                mma16816(o[2 * i],     pah, &vf[0]);
                mma16816(o[2 * i],     pal, &vf[0]);
                mma16816(o[2 * i + 1], pah, &vf[2]);
                mma16816(o[2 * i + 1], pal, &vf[2]);
            }
        }

        __syncthreads();
        if (j + 2 < jmax) loadKV(j + 2, st);
    }

    // ---- epilogue: normalize, single fp16, write (b,t,c) ----
    const float inv0 = 1.f / l0, inv1 = 1.f / l1;
    const size_t r0base = ((size_t)b * TT + qg0) * CC + h * HD;
    const size_t r1base = ((size_t)b * TT + qg1) * CC + h * HD;
#pragma unroll
    for (int n = 0; n < 16; n++) {
        const int d = 8 * n + 2 * (lane & 3);
        *(uint32_t*)&outp[r0base + d] = pack_h2(o[n][0] * inv0, o[n][1] * inv0);
        *(uint32_t*)&outp[r1base + d] = pack_h2(o[n][2] * inv1, o[n][3] * inv1);
    }
}

// ---------------------------------------------------------------------------
// Launcher
// ---------------------------------------------------------------------------
extern "C" void kernel_launch(void* const* d_in, const int* in_sizes, int n_in,
                              void* d_out, int out_size)
{
    const float* x    = (const float*)d_in[0];
    const float* mask = (const float*)d_in[1];
    const float* bq   = (const float*)d_in[3];
    const float* bk   = (const float*)d_in[5];
    const float* bv   = (const float*)d_in[7];
    const float* bp   = (const float*)d_in[9];
    const float* W[4] = {(const float*)d_in[2], (const float*)d_in[4],
                         (const float*)d_in[6], (const float*)d_in[8]};
    float* out = (float*)d_out;

    __half *xh, *xl, *at, *w, *qh, *ql, *kh, *vhp;
    cudaGetSymbolAddress((void**)&xh,  g_xh);
    cudaGetSymbolAddress((void**)&xl,  g_xl);
    cudaGetSymbolAddress((void**)&at,  g_at);
    cudaGetSymbolAddress((void**)&w,   g_w);
    cudaGetSymbolAddress((void**)&qh,  g_qh);
    cudaGetSymbolAddress((void**)&ql,  g_ql);
    cudaGetSymbolAddress((void**)&kh,  g_kh);
    cudaGetSymbolAddress((void**)&vhp, g_vh);

    cudaFuncSetAttribute(gemm_qkv_kernel,
                         cudaFuncAttributeMaxDynamicSharedMemorySize, GEMM_SMEM);
    cudaFuncSetAttribute(gemm1_tc_kernel,
                         cudaFuncAttributeMaxDynamicSharedMemorySize, GEMM1_SMEM);
    cudaFuncSetAttribute(attn_tc_kernel,
                         cudaFuncAttributeMaxDynamicSharedMemorySize, ATT_SMEM);

    // 1. split x to fp16 hi/lo; convert weights to fp16
    {
        const int n4x = (BB * TT * CC) / 4;
        split_kernel<<<(n4x + 255) / 256, 256>>>(x, xh, xl, n4x);
        const int n4w = (CC * CC) / 4;
        for (int i = 0; i < 4; i++)
            conv_kernel<<<(n4w + 255) / 256, 256>>>(W[i], w + (size_t)i * CC * CC, n4w);
    }

    // 2. fused QKV projection (Q split + pre-scaled; K,V single fp16)
    gemm_qkv_kernel<<<dim3(48, MROWS / BM), 256, GEMM_SMEM>>>(
        xh, xl, w, bq, bk, bv, qh, ql, kh, vhp);

    // 3. flash attention -> single fp16 (b,t,c)
    attn_tc_kernel<<<dim3(TT / 128, BB * NH), 256, ATT_SMEM>>>(
        qh, ql, kh, vhp, mask, at);

    // 4. output projection (1-pass) -> fp32 out
    gemm1_tc_kernel<<<dim3(CC / BN, MROWS / BM), 256, GEMM1_SMEM>>>(
        at, w + 3 * (size_t)CC * CC, bp, out);
}

// round 12
// speedup vs baseline: 13.0159x; 1.4212x over previous
#include <cuda_runtime.h>
#include <cuda_fp16.h>
#include <math.h>
#include <stdint.h>
#include <stddef.h>

// Problem constants
#define BB   4
#define TT   2048
#define CC   2048
#define NH   16
#define HD   128
#define MROWS (BB * TT)          // 8192
#define LOG2E 1.4426950408889634f
#define QSCALE 0.12751743502016435f   // (1/sqrt(128)) * log2(e)

// ---------------------------------------------------------------------------
// Scratch (device globals)
// ---------------------------------------------------------------------------
__device__ __half g_x[BB * TT * CC];       // x single fp16
__device__ __half g_at[BB * TT * CC];      // attention out, single fp16
__device__ __half g_w[4][CC * CC];         // weights, single fp16
__device__ __half g_qh[BB * NH * TT * HD]; // (b,h,t,d) Q split hi
__device__ __half g_ql[BB * NH * TT * HD]; // Q split lo
__device__ __half g_kh[BB * NH * TT * HD]; // K single fp16
__device__ __half g_vh[BB * NH * TT * HD]; // V single fp16

// ---------------------------------------------------------------------------
// Helpers
// ---------------------------------------------------------------------------
__device__ __forceinline__ uint32_t smem_u32(const void* p) {
    uint32_t a;
    asm("{ .reg .u64 t; cvta.to.shared.u64 t, %1; cvt.u32.u64 %0, t; }"
        : "=r"(a) : "l"(p));
    return a;
}
__device__ __forceinline__ void cp16(uint32_t dst, const void* src) {
    asm volatile("cp.async.cg.shared.global [%0], [%1], 16;"
                 :: "r"(dst), "l"(src) : "memory");
}
__device__ __forceinline__ void ldsm_x4(uint32_t* r, uint32_t addr) {
    asm volatile("ldmatrix.sync.aligned.m8n8.x4.shared.b16 {%0,%1,%2,%3}, [%4];"
        : "=r"(r[0]), "=r"(r[1]), "=r"(r[2]), "=r"(r[3]) : "r"(addr));
}
__device__ __forceinline__ void ldsm_x4t(uint32_t* r, uint32_t addr) {
    asm volatile("ldmatrix.sync.aligned.m8n8.x4.trans.shared.b16 {%0,%1,%2,%3}, [%4];"
        : "=r"(r[0]), "=r"(r[1]), "=r"(r[2]), "=r"(r[3]) : "r"(addr));
}
// fp16 MMA m16n8k16, fp32 accumulate
__device__ __forceinline__ void mma16816(float* c, const uint32_t* a, const uint32_t* b) {
    asm volatile("mma.sync.aligned.m16n8k16.row.col.f32.f16.f16.f32 "
        "{%0,%1,%2,%3}, {%4,%5,%6,%7}, {%8,%9}, {%0,%1,%2,%3};"
        : "+f"(c[0]), "+f"(c[1]), "+f"(c[2]), "+f"(c[3])
        : "r"(a[0]), "r"(a[1]), "r"(a[2]), "r"(a[3]), "r"(b[0]), "r"(b[1]));
}
// pack (a,b) -> fp16x2 hi word + lo word (a in low half)
__device__ __forceinline__ void split_pack(float a, float b, uint32_t& h, uint32_t& l) {
    __half ah = __float2half_rn(a);
    __half bh = __float2half_rn(b);
    __half2 hh; hh.x = ah; hh.y = bh;
    h = *(uint32_t*)&hh;
    __half2 ll;
    ll.x = __float2half_rn(a - __half2float(ah));
    ll.y = __float2half_rn(b - __half2float(bh));
    l = *(uint32_t*)&ll;
}
__device__ __forceinline__ uint32_t pack_h2(float a, float b) {
    __half2 hh; hh.x = __float2half_rn(a); hh.y = __float2half_rn(b);
    return *(uint32_t*)&hh;
}

// ---------------------------------------------------------------------------
// fp32 -> fp16 single convert
// ---------------------------------------------------------------------------
__global__ void conv_kernel(const float* __restrict__ in,
                            __half* __restrict__ out, int n4)
{
    int i = blockIdx.x * blockDim.x + threadIdx.x;
    if (i >= n4) return;
    float4 v = ((const float4*)in)[i];
    __align__(8) __half h[4];
    h[0] = __float2half_rn(v.x); h[1] = __float2half_rn(v.y);
    h[2] = __float2half_rn(v.z); h[3] = __float2half_rn(v.w);
    ((uint2*)out)[i] = *(uint2*)h;
}

// 4 weight matrices in one launch (dst contiguous)
__global__ void conv4_kernel(const float* __restrict__ w0, const float* __restrict__ w1,
                             const float* __restrict__ w2, const float* __restrict__ w3,
                             __half* __restrict__ out)
{
    const int per = (CC * CC) / 4;           // float4s per matrix
    int i = blockIdx.x * blockDim.x + threadIdx.x;
    if (i >= 4 * per) return;
    const int m = i / per, r = i % per;
    const float* src = (m == 0) ? w0 : (m == 1) ? w1 : (m == 2) ? w2 : w3;
    float4 v = ((const float4*)src)[r];
    __align__(8) __half h[4];
    h[0] = __float2half_rn(v.x); h[1] = __float2half_rn(v.y);
    h[2] = __float2half_rn(v.z); h[3] = __float2half_rn(v.w);
    ((uint2*)out)[i] = *(uint2*)h;
}

// ---------------------------------------------------------------------------
// Common GEMM geometry
// ---------------------------------------------------------------------------
#define BM 128
#define BN 128
#define BK 64
#define KCH (CC / BK)                 // 32
#define TILE_B 16384                  // 128 rows x 128 bytes
#define NSTG 4
#define STG_B (2 * TILE_B)            // A, W
static constexpr unsigned GEMM_SMEM = NSTG * STG_B;   // 131072

// ---------------------------------------------------------------------------
// Fused QKV GEMM (1-pass fp16):
//   grid (48, 64); bx>>4 selects {Q,K,V}; bx&15 = head/N-tile.
//   Q -> split hi/lo (pre-scaled QSCALE); K,V -> single fp16, head layout.
// ---------------------------------------------------------------------------
__global__ __launch_bounds__(256, 1)
void gemm_qkv_kernel(const __half* __restrict__ X,
                     const __half* __restrict__ Wbase,
                     const float* __restrict__ bq,
                     const float* __restrict__ bk,
                     const float* __restrict__ bv,
                     __half* __restrict__ qh, __half* __restrict__ ql,
                     __half* __restrict__ kh, __half* __restrict__ vh)
{
    extern __shared__ char smem[];
    const uint32_t sb = smem_u32(smem);
    const int tid  = threadIdx.x;
    const int lane = tid & 31;
    const int wid  = tid >> 5;
    const int wr   = wid >> 2;
    const int wc   = wid & 3;
    const int bx = blockIdx.x, by = blockIdx.y;
    const int sel = bx >> 4;              // 0=Q, 1=K, 2=V
    const int hx  = bx & 15;              // head / N-tile

    const float* bias = (sel == 0) ? bq : (sel == 1) ? bk : bv;
    const float escale = (sel == 0) ? QSCALE : 1.0f;

    const __half* srcs[2] = {
        X + (size_t)by * BM * CC,
        Wbase + (size_t)sel * CC * CC + (size_t)hx * BN * CC
    };

    auto load_stage = [&](int stg, int kc) {
        const uint32_t base = sb + stg * STG_B;
#pragma unroll
        for (int ti = 0; ti < 2; ti++) {
            const __half* src = srcs[ti];
            const uint32_t tb = base + ti * TILE_B;
#pragma unroll
            for (int i = 0; i < 4; i++) {
                const int idx = tid + i * 256;
                const int row = idx >> 3;
                const int ch  = idx & 7;
                const uint32_t dst = tb + row * 128 + ((ch ^ (row & 7)) << 4);
                cp16(dst, src + (size_t)row * CC + kc + ch * 8);
            }
        }
        asm volatile("cp.async.commit_group;" ::: "memory");
    };

    const int a_lr = lane & 15;
    const int a_hk = lane >> 4;
    uint32_t a_off[4]; int a_sel[4];
#pragma unroll
    for (int mt = 0; mt < 4; mt++) {
        const int r = wr * 64 + mt * 16 + a_lr;
        a_off[mt] = r * 128;
        a_sel[mt] = r & 7;
    }
    const int b_rloc = ((lane >> 4) << 3) + (lane & 7);
    const int b_ch   = (lane >> 3) & 1;
    uint32_t b_off[2]; int b_sel2[2];
#pragma unroll
    for (int ntp = 0; ntp < 2; ntp++) {
        const int r = wc * 32 + ntp * 16 + b_rloc;
        b_off[ntp] = r * 128;
        b_sel2[ntp] = r & 7;
    }

    float c[4][4][4];
#pragma unroll
    for (int mt = 0; mt < 4; mt++)
#pragma unroll
        for (int nt = 0; nt < 4; nt++)
#pragma unroll
            for (int i = 0; i < 4; i++) c[mt][nt][i] = 0.f;

    load_stage(0, 0);
    load_stage(1, BK);
    load_stage(2, 2 * BK);

    for (int chk = 0; chk < KCH; chk++) {
        const int rem = KCH - 1 - chk;
        if (rem >= 2)      asm volatile("cp.async.wait_group 2;" ::: "memory");
        else if (rem == 1) asm volatile("cp.async.wait_group 1;" ::: "memory");
        else               asm volatile("cp.async.wait_group 0;" ::: "memory");
        __syncthreads();

        const uint32_t base = sb + (chk % NSTG) * STG_B;
#pragma unroll
        for (int ks = 0; ks < 4; ks++) {
            uint32_t ah[4][4], bf[2][4];
            const int ca = ks * 2 + a_hk;
            const int cb = ks * 2 + b_ch;
#pragma unroll
            for (int mt = 0; mt < 4; mt++)
                ldsm_x4(ah[mt], base + a_off[mt] + (uint32_t)(((ca ^ a_sel[mt])) << 4));
#pragma unroll
            for (int ntp = 0; ntp < 2; ntp++)
                ldsm_x4(bf[ntp], base + TILE_B + b_off[ntp] + (uint32_t)(((cb ^ b_sel2[ntp])) << 4));
#pragma unroll
            for (int mt = 0; mt < 4; mt++)
#pragma unroll
                for (int nt = 0; nt < 4; nt++)
                    mma16816(c[mt][nt], ah[mt], &bf[nt >> 1][(nt & 1) * 2]);
        }

        if (chk + 3 < KCH) load_stage((chk + 3) % NSTG, (chk + 3) * BK);
    }

    // ---- epilogue (head layout) ----
    const int t4 = lane >> 2;
    const int t2 = (lane & 3) * 2;
#pragma unroll
    for (int mt = 0; mt < 4; mt++) {
        const int r0 = by * BM + wr * 64 + mt * 16 + t4;
        const int r1 = r0 + 8;
#pragma unroll
        for (int nt = 0; nt < 4; nt++) {
            const int col = hx * BN + wc * 32 + nt * 8 + t2;
            const float bi0 = bias[col], bi1 = bias[col + 1];
            const float v00 = (c[mt][nt][0] + bi0) * escale;
            const float v01 = (c[mt][nt][1] + bi1) * escale;
            const float v10 = (c[mt][nt][2] + bi0) * escale;
            const float v11 = (c[mt][nt][3] + bi1) * escale;
            const int d = col & 127;
            const int b0 = r0 >> 11, t0 = r0 & 2047;
            const int b1 = r1 >> 11, t1 = r1 & 2047;
            const size_t i0 = (((size_t)(b0 * NH + hx)) * TT + t0) * HD + d;
            const size_t i1 = (((size_t)(b1 * NH + hx)) * TT + t1) * HD + d;
            if (sel == 0) {
                uint32_t ph, pl;
                split_pack(v00, v01, ph, pl);
                *(uint32_t*)&qh[i0] = ph; *(uint32_t*)&ql[i0] = pl;
                split_pack(v10, v11, ph, pl);
                *(uint32_t*)&qh[i1] = ph; *(uint32_t*)&ql[i1] = pl;
            } else {
                __half* o = (sel == 1) ? kh : vh;
                *(uint32_t*)&o[i0] = pack_h2(v00, v01);
                *(uint32_t*)&o[i1] = pack_h2(v10, v11);
            }
        }
    }
}

// ---------------------------------------------------------------------------
// 1-pass fp16 GEMM (output projection): out = att @ Wp^T + bp, fp32 out.
// grid (16, 64).
// ---------------------------------------------------------------------------
__global__ __launch_bounds__(256, 1)
void gemm1_tc_kernel(const __half* __restrict__ A,
                     const __half* __restrict__ W,
                     const float* __restrict__ bias,
                     float* __restrict__ out)
{
    extern __shared__ char smem[];
    const uint32_t sb = smem_u32(smem);
    const int tid  = threadIdx.x;
    const int lane = tid & 31;
    const int wid  = tid >> 5;
    const int wr   = wid >> 2;
    const int wc   = wid & 3;
    const int bx = blockIdx.x, by = blockIdx.y;

    const __half* srcs[2] = {
        A + (size_t)by * BM * CC,
        W + (size_t)bx * BN * CC
    };

    auto load_stage = [&](int stg, int kc) {
        const uint32_t base = sb + stg * STG_B;
#pragma unroll
        for (int ti = 0; ti < 2; ti++) {
            const __half* src = srcs[ti];
            const uint32_t tb = base + ti * TILE_B;
#pragma unroll
            for (int i = 0; i < 4; i++) {
                const int idx = tid + i * 256;
                const int row = idx >> 3;
                const int ch  = idx & 7;
                const uint32_t dst = tb + row * 128 + ((ch ^ (row & 7)) << 4);
                cp16(dst, src + (size_t)row * CC + kc + ch * 8);
            }
        }
        asm volatile("cp.async.commit_group;" ::: "memory");
    };

    const int a_lr = lane & 15;
    const int a_hk = lane >> 4;
    uint32_t a_off[4]; int a_sel[4];
#pragma unroll
    for (int mt = 0; mt < 4; mt++) {
        const int r = wr * 64 + mt * 16 + a_lr;
        a_off[mt] = r * 128;
        a_sel[mt] = r & 7;
    }
    const int b_rloc = ((lane >> 4) << 3) + (lane & 7);
    const int b_ch   = (lane >> 3) & 1;
    uint32_t b_off[2]; int b_sel2[2];
#pragma unroll
    for (int ntp = 0; ntp < 2; ntp++) {
        const int r = wc * 32 + ntp * 16 + b_rloc;
        b_off[ntp] = r * 128;
        b_sel2[ntp] = r & 7;
    }

    float c[4][4][4];
#pragma unroll
    for (int mt = 0; mt < 4; mt++)
#pragma unroll
        for (int nt = 0; nt < 4; nt++)
#pragma unroll
            for (int i = 0; i < 4; i++) c[mt][nt][i] = 0.f;

    load_stage(0, 0);
    load_stage(1, BK);
    load_stage(2, 2 * BK);

    for (int chk = 0; chk < KCH; chk++) {
        const int rem = KCH - 1 - chk;
        if (rem >= 2)      asm volatile("cp.async.wait_group 2;" ::: "memory");
        else if (rem == 1) asm volatile("cp.async.wait_group 1;" ::: "memory");
        else               asm volatile("cp.async.wait_group 0;" ::: "memory");
        __syncthreads();

        const uint32_t base = sb + (chk % NSTG) * STG_B;
#pragma unroll
        for (int ks = 0; ks < 4; ks++) {
            uint32_t ah[4][4], bf[2][4];
            const int ca = ks * 2 + a_hk;
            const int cb = ks * 2 + b_ch;
#pragma unroll
            for (int mt = 0; mt < 4; mt++)
                ldsm_x4(ah[mt], base + a_off[mt] + (uint32_t)(((ca ^ a_sel[mt])) << 4));
#pragma unroll
            for (int ntp = 0; ntp < 2; ntp++)
                ldsm_x4(bf[ntp], base + TILE_B + b_off[ntp] + (uint32_t)(((cb ^ b_sel2[ntp])) << 4));
#pragma unroll
            for (int mt = 0; mt < 4; mt++)
#pragma unroll
                for (int nt = 0; nt < 4; nt++)
                    mma16816(c[mt][nt], ah[mt], &bf[nt >> 1][(nt & 1) * 2]);
        }

        if (chk + 3 < KCH) load_stage((chk + 3) % NSTG, (chk + 3) * BK);
    }

    const int t4 = lane >> 2;
    const int t2 = (lane & 3) * 2;
#pragma unroll
    for (int mt = 0; mt < 4; mt++) {
        const int r0 = by * BM + wr * 64 + mt * 16 + t4;
        const int r1 = r0 + 8;
#pragma unroll
        for (int nt = 0; nt < 4; nt++) {
            const int col = bx * BN + wc * 32 + nt * 8 + t2;
            const float bi0 = bias[col], bi1 = bias[col + 1];
            float2 v0 = {c[mt][nt][0] + bi0, c[mt][nt][1] + bi1};
            float2 v1 = {c[mt][nt][2] + bi0, c[mt][nt][3] + bi1};
            *(float2*)(out + (size_t)r0 * CC + col) = v0;
            *(float2*)(out + (size_t)r1 * CC + col) = v1;
        }
    }
}

// ---------------------------------------------------------------------------
// Tensor-core flash attention, fp16, exp2 domain.
// Grid: (T/128, B*H). 256 threads = 8 warps x 16 query rows.
// Q split (2-pass QK), K single, P single (1-pass PV), V single.
// KV tiles of 64, double-buffered cp.async. Output: single fp16 (b,t,c).
// Smem: Qh[0:32K], Ql[32K:64K], stage s at 64K + 32K*s: {K:0, V:16K}.
// ---------------------------------------------------------------------------
static constexpr unsigned ATT_SMEM = 131072;

__global__ __launch_bounds__(256, 1)
void attn_tc_kernel(const __half* __restrict__ qh, const __half* __restrict__ ql,
                    const __half* __restrict__ kh, const __half* __restrict__ vh,
                    const float* __restrict__ mask,
                    __half* __restrict__ outp)
{
    extern __shared__ char smem[];
    const uint32_t sb = smem_u32(smem);
    const int tid = threadIdx.x, lane = tid & 31, warp = tid >> 5;
    const int qb = gridDim.x - 1 - blockIdx.x;     // long CTAs first
    const int bh = blockIdx.y;
    const int b = bh >> 4, h = bh & 15;
    const int q0 = qb * 128;
    const int jmax = 2 * qb + 2;
    const size_t bhoff = (size_t)bh * TT * HD;

    // ---- Q tile load (hi + lo) ----
    {
        const __half* s0 = qh + bhoff + (size_t)q0 * HD;
        const __half* s1 = ql + bhoff + (size_t)q0 * HD;
#pragma unroll
        for (int i = 0; i < 8; i++) {
            const int idx = tid + i * 256;
            const int r = idx >> 4, ch = idx & 15;
            const uint32_t off = r * 256 + ((ch ^ (r & 7)) << 4);
            cp16(sb + off,         s0 + (size_t)r * HD + ch * 8);
            cp16(sb + 32768 + off, s1 + (size_t)r * HD + ch * 8);
        }
        asm volatile("cp.async.commit_group;" ::: "memory");
    }

    auto loadKV = [&](int j, int st) {
        const uint32_t base = sb + 65536 + st * 32768;
        const int kv0 = j * 64;
        const __half* srcs[2] = {
            kh + bhoff + (size_t)kv0 * HD, vh + bhoff + (size_t)kv0 * HD };
#pragma unroll
        for (int i = 0; i < 8; i++) {
            const int idx = tid + i * 256;
            const int mat = idx >> 10, r = (idx >> 4) & 63, ch = idx & 15;
            cp16(base + mat * 16384 + r * 256 + ((ch ^ (r & 7)) << 4),
                 srcs[mat] + (size_t)r * HD + ch * 8);
        }
        asm volatile("cp.async.commit_group;" ::: "memory");
    };

    loadKV(0, 0);
    loadKV(1, 1);

    float o[16][4];
#pragma unroll
    for (int n = 0; n < 16; n++)
#pragma unroll
        for (int i = 0; i < 4; i++) o[n][i] = 0.f;
    float m0 = -1e30f, m1 = -1e30f, l0 = 0.f, l1 = 0.f;

    const int qrow  = warp * 16 + (lane & 15);
    const uint32_t a_base = qrow * 256;
    const int a_sel = qrow & 7;
    const int a_kh  = lane >> 4;
    const int kb_rloc = ((lane >> 4) << 3) + (lane & 7);
    const int kb_ch   = (lane >> 3) & 1;
    const int v_rloc  = lane & 15;
    const int v_chh   = lane >> 4;

    const int qg0 = q0 + warp * 16 + (lane >> 2);
    const int qg1 = qg0 + 8;

    for (int j = 0; j < jmax; j++) {
        const int kv0 = j * 64;
        const int st = j & 1;
        if (j + 1 < jmax) asm volatile("cp.async.wait_group 1;" ::: "memory");
        else              asm volatile("cp.async.wait_group 0;" ::: "memory");
        __syncthreads();

        const uint32_t KB = sb + 65536 + st * 32768;
        const uint32_t VB = KB + 16384;

        // ---- S = Q K^T (2 split passes, Q exact), 16x64 per warp ----
        float s[8][4];
#pragma unroll
        for (int n = 0; n < 8; n++)
#pragma unroll
            for (int i = 0; i < 4; i++) s[n][i] = 0.f;

#pragma unroll
        for (int ks = 0; ks < 8; ks++) {
            uint32_t qfh[4], qfl[4];
            const uint32_t ca = (uint32_t)(((2 * ks + a_kh) ^ a_sel) << 4);
            ldsm_x4(qfh, sb + a_base + ca);
            ldsm_x4(qfl, sb + 32768 + a_base + ca);
            uint32_t kf[16];
#pragma unroll
            for (int i = 0; i < 4; i++) {
                const int r = 16 * i + kb_rloc;
                const uint32_t off = r * 256 + (((2 * ks + kb_ch) ^ (r & 7)) << 4);
                ldsm_x4(&kf[4 * i], KB + off);
            }
#pragma unroll
            for (int n = 0; n < 8; n++) {
                mma16816(s[n], qfh, &kf[2 * n]);
                mma16816(s[n], qfl, &kf[2 * n]);
            }
        }

        // ---- mask + causal ----
        const bool need_mask = (j >= 2 * qb);
#pragma unroll
        for (int n = 0; n < 8; n++) {
            const int kg = kv0 + 8 * n + 2 * (lane & 3);
            const float2 mv = *(const float2*)&mask[b * TT + kg];
            const float am0 = mv.x * LOG2E, am1 = mv.y * LOG2E;
            s[n][0] += am0; s[n][1] += am1;
            s[n][2] += am0; s[n][3] += am1;
            if (need_mask) {
                if (kg     > qg0) s[n][0] = -1e30f;
                if (kg + 1 > qg0) s[n][1] = -1e30f;
                if (kg     > qg1) s[n][2] = -1e30f;
                if (kg + 1 > qg1) s[n][3] = -1e30f;
            }
        }

        // ---- online softmax (quad-local) ----
        float mx0 = m0, mx1 = m1;
#pragma unroll
        for (int n = 0; n < 8; n++) {
            mx0 = fmaxf(mx0, fmaxf(s[n][0], s[n][1]));
            mx1 = fmaxf(mx1, fmaxf(s[n][2], s[n][3]));
        }
        mx0 = fmaxf(mx0, __shfl_xor_sync(0xffffffffu, mx0, 1));
        mx0 = fmaxf(mx0, __shfl_xor_sync(0xffffffffu, mx0, 2));
        mx1 = fmaxf(mx1, __shfl_xor_sync(0xffffffffu, mx1, 1));
        mx1 = fmaxf(mx1, __shfl_xor_sync(0xffffffffu, mx1, 2));
        const float al0 = exp2f(m0 - mx0);
        const float al1 = exp2f(m1 - mx1);
        m0 = mx0; m1 = mx1;
        float sum0 = 0.f, sum1 = 0.f;
#pragma unroll
        for (int n = 0; n < 8; n++) {
            s[n][0] = exp2f(s[n][0] - m0);
            s[n][1] = exp2f(s[n][1] - m0);
            s[n][2] = exp2f(s[n][2] - m1);
            s[n][3] = exp2f(s[n][3] - m1);
            sum0 += s[n][0] + s[n][1];
            sum1 += s[n][2] + s[n][3];
        }
        sum0 += __shfl_xor_sync(0xffffffffu, sum0, 1);
        sum0 += __shfl_xor_sync(0xffffffffu, sum0, 2);
        sum1 += __shfl_xor_sync(0xffffffffu, sum1, 1);
        sum1 += __shfl_xor_sync(0xffffffffu, sum1, 2);
        l0 = l0 * al0 + sum0;
        l1 = l1 * al1 + sum1;
#pragma unroll
        for (int n = 0; n < 16; n++) {
            o[n][0] *= al0; o[n][1] *= al0;
            o[n][2] *= al1; o[n][3] *= al1;
        }

        // ---- O += P V (register repack, P single, 1 pass) ----
#pragma unroll
        for (int kv = 0; kv < 4; kv++) {
            uint32_t pa[4];
            pa[0] = pack_h2(s[2 * kv][0],     s[2 * kv][1]);
            pa[1] = pack_h2(s[2 * kv][2],     s[2 * kv][3]);
            pa[2] = pack_h2(s[2 * kv + 1][0], s[2 * kv + 1][1]);
            pa[3] = pack_h2(s[2 * kv + 1][2], s[2 * kv + 1][3]);
            const int vr = 16 * kv + v_rloc;
            const uint32_t vro = vr * 256;
            const int vsel = vr & 7;
#pragma unroll
            for (int i = 0; i < 8; i++) {
                const uint32_t ch = (uint32_t)(((2 * i + v_chh) ^ vsel) << 4);
                uint32_t vf[4];
                ldsm_x4t(vf, VB + vro + ch);
                mma16816(o[2 * i],     pa, &vf[0]);
                mma16816(o[2 * i + 1], pa, &vf[2]);
            }
        }

        __syncthreads();
        if (j + 2 < jmax) loadKV(j + 2, st);
    }

    // ---- epilogue: normalize, single fp16, write (b,t,c) ----
    const float inv0 = 1.f / l0, inv1 = 1.f / l1;
    const size_t r0base = ((size_t)b * TT + qg0) * CC + h * HD;
    const size_t r1base = ((size_t)b * TT + qg1) * CC + h * HD;
#pragma unroll
    for (int n = 0; n < 16; n++) {
        const int d = 8 * n + 2 * (lane & 3);
        *(uint32_t*)&outp[r0base + d] = pack_h2(o[n][0] * inv0, o[n][1] * inv0);
        *(uint32_t*)&outp[r1base + d] = pack_h2(o[n][2] * inv1, o[n][3] * inv1);
    }
}

// ---------------------------------------------------------------------------
// Launcher
// ---------------------------------------------------------------------------
extern "C" void kernel_launch(void* const* d_in, const int* in_sizes, int n_in,
                              void* d_out, int out_size)
{
    const float* x    = (const float*)d_in[0];
    const float* mask = (const float*)d_in[1];
    const float* bq   = (const float*)d_in[3];
    const float* bk   = (const float*)d_in[5];
    const float* bv   = (const float*)d_in[7];
    const float* bp   = (const float*)d_in[9];
    float* out = (float*)d_out;

    __half *xp, *at, *w, *qh, *ql, *kh, *vhp;
    cudaGetSymbolAddress((void**)&xp,  g_x);
    cudaGetSymbolAddress((void**)&at,  g_at);
    cudaGetSymbolAddress((void**)&w,   g_w);
    cudaGetSymbolAddress((void**)&qh,  g_qh);
    cudaGetSymbolAddress((void**)&ql,  g_ql);
    cudaGetSymbolAddress((void**)&kh,  g_kh);
    cudaGetSymbolAddress((void**)&vhp, g_vh);

    cudaFuncSetAttribute(gemm_qkv_kernel,
                         cudaFuncAttributeMaxDynamicSharedMemorySize, GEMM_SMEM);
    cudaFuncSetAttribute(gemm1_tc_kernel,
                         cudaFuncAttributeMaxDynamicSharedMemorySize, GEMM_SMEM);
    cudaFuncSetAttribute(attn_tc_kernel,
                         cudaFuncAttributeMaxDynamicSharedMemorySize, ATT_SMEM);

    // 1. convert x and weights to fp16
    {
        const int n4x = (BB * TT * CC) / 4;
        conv_kernel<<<(n4x + 255) / 256, 256>>>(x, xp, n4x);
        const int n4w = CC * CC;          // total float4s over 4 matrices
        conv4_kernel<<<(n4w + 255) / 256, 256>>>(
            (const float*)d_in[2], (const float*)d_in[4],
            (const float*)d_in[6], (const float*)d_in[8], w);
    }

    // 2. fused QKV projection (1-pass; Q split + pre-scaled; K,V single fp16)
    gemm_qkv_kernel<<<dim3(48, MROWS / BM), 256, GEMM_SMEM>>>(
        xp, w, bq, bk, bv, qh, ql, kh, vhp);

    // 3. flash attention -> single fp16 (b,t,c)
    attn_tc_kernel<<<dim3(TT / 128, BB * NH), 256, ATT_SMEM>>>(
        qh, ql, kh, vhp, mask, at);

    // 4. output projection (1-pass) -> fp32 out
    gemm1_tc_kernel<<<dim3(CC / BN, MROWS / BM), 256, GEMM_SMEM>>>(
        at, w + 3 * (size_t)CC * CC, bp, out);
}